// round 2
// baseline (speedup 1.0000x reference)
#include <cuda_runtime.h>
#include <math.h>

#define B_    32
#define N_IMG 196
#define M_TOK 256
#define D_    1024
#define NM    (N_IMG*M_TOK)

// ---------------- device scratch (allocation-free) ----------------
__device__ float g_xn[B_*N_IMG*D_];
__device__ float g_yn[B_*M_TOK*D_];
__device__ float g_Cxy[B_*NM];
__device__ float g_Cs [B_*N_IMG*N_IMG];
__device__ float g_Ct [B_*M_TOK*M_TOK];
__device__ float g_gamma[B_*NM];
__device__ float g_tmp  [B_*NM];
__device__ float g_Cg   [B_*NM];
__device__ float g_cstrow[B_*N_IMG];
__device__ float g_cstcol[B_*M_TOK];
__device__ unsigned g_minmax[6];
__device__ float g_dotwd[B_];
__device__ float g_dotgw[B_];

// order-preserving float<->uint encoding (for atomic min/max incl. negatives)
__device__ __forceinline__ unsigned enc_mono(float f){
    unsigned u = __float_as_uint(f);
    return (u & 0x80000000u) ? ~u : (u | 0x80000000u);
}
__device__ __forceinline__ float dec_mono(unsigned e){
    unsigned u = (e & 0x80000000u) ? (e ^ 0x80000000u) : ~e;
    return __uint_as_float(u);
}

// ---------------- init (must run every launch: graph replays) ----------------
__global__ void init_kernel(){
    int t = threadIdx.x;
    if (t < 3){ g_minmax[2*t] = 0xFFFFFFFFu; g_minmax[2*t+1] = 0u; }
}

// ---------------- per-position L2 normalize over D (with optional mask) ----------------
__global__ void normalize_kernel(const float* __restrict__ x,
                                 const float* __restrict__ mask,
                                 float* __restrict__ outp, int npos)
{
    const int bp  = blockIdx.x;
    const int b   = bp / npos;
    const int pos = bp - b*npos;
    const float* v = x + (size_t)bp * D_;
    const float mk = mask ? mask[(size_t)b*npos + pos] : 1.0f;

    float ss = 0.f;
    for (int d = threadIdx.x; d < D_; d += blockDim.x){
        float t = v[d] * mk;
        ss += t*t;
    }
    #pragma unroll
    for (int o = 16; o; o >>= 1) ss += __shfl_xor_sync(0xffffffffu, ss, o);
    __shared__ float sred[8];
    if ((threadIdx.x & 31) == 0) sred[threadIdx.x >> 5] = ss;
    __syncthreads();
    __shared__ float s_inv;
    if (threadIdx.x == 0){
        float t = 0.f;
        for (int w = 0; w < 8; ++w) t += sred[w];
        s_inv = 1.0f / (sqrtf(t) + 1e-12f);
    }
    __syncthreads();
    const float scale = s_inv * mk;
    float* o = outp + (size_t)bp * D_;
    for (int d = threadIdx.x; d < D_; d += blockDim.x)
        o[d] = v[d] * scale;
}

// ---------------- tiled batched fp32 GEMM ----------------
// BLAYOUT 0: B is [N][K] row-major (NT: dot of rows). 1: B is [K][N] (NN).
// EPI 0: out = 1 - acc, track global min/max into g_minmax[2*mmIdx..]
// EPI 1: out = acc
// EPI 2: out = rowadd[b,i] + coladd[b,j] - 2*acc
template<int BLAYOUT, int EPI>
__global__ void __launch_bounds__(256)
gemm_kernel(const float* __restrict__ Aall, const float* __restrict__ Ball,
            float* __restrict__ Call, int Mz, int Nz, int Kz,
            const float* __restrict__ rowadd, const float* __restrict__ coladd,
            int mmIdx)
{
    const int b = blockIdx.z;
    const float* A  = Aall + (size_t)b * Mz * Kz;
    const float* Bp = Ball + (size_t)b * Nz * Kz;
    float* Cp       = Call + (size_t)b * Mz * Nz;
    const int i0 = blockIdx.y * 64, j0 = blockIdx.x * 64;

    __shared__ __align__(16) float As[16][68];
    __shared__ __align__(16) float Bs[16][68];

    const int tid = threadIdx.x;
    const int tx = tid & 15, ty = tid >> 4;
    float acc[4][4];
    #pragma unroll
    for (int u = 0; u < 4; ++u)
        #pragma unroll
        for (int v = 0; v < 4; ++v) acc[u][v] = 0.f;

    for (int k0 = 0; k0 < Kz; k0 += 16){
        #pragma unroll
        for (int p = 0; p < 4; ++p){
            int idx = tid + p*256;
            int kk = idx & 15, ii = idx >> 4;
            float v = 0.f;
            if (i0+ii < Mz && k0+kk < Kz) v = A[(size_t)(i0+ii)*Kz + (k0+kk)];
            As[kk][ii] = v;
        }
        if (BLAYOUT == 0){
            #pragma unroll
            for (int p = 0; p < 4; ++p){
                int idx = tid + p*256;
                int kk = idx & 15, jj = idx >> 4;
                float v = 0.f;
                if (j0+jj < Nz && k0+kk < Kz) v = Bp[(size_t)(j0+jj)*Kz + (k0+kk)];
                Bs[kk][jj] = v;
            }
        } else {
            #pragma unroll
            for (int p = 0; p < 4; ++p){
                int idx = tid + p*256;
                int jj = idx & 63, kk = idx >> 6;
                float v = 0.f;
                if (k0+kk < Kz && j0+jj < Nz) v = Bp[(size_t)(k0+kk)*Nz + (j0+jj)];
                Bs[kk][jj] = v;
            }
        }
        __syncthreads();
        #pragma unroll
        for (int kk = 0; kk < 16; ++kk){
            float4 a4 = *(const float4*)&As[kk][ty*4];
            float4 b4 = *(const float4*)&Bs[kk][tx*4];
            float a[4]  = {a4.x, a4.y, a4.z, a4.w};
            float bb[4] = {b4.x, b4.y, b4.z, b4.w};
            #pragma unroll
            for (int u = 0; u < 4; ++u)
                #pragma unroll
                for (int v = 0; v < 4; ++v)
                    acc[u][v] = fmaf(a[u], bb[v], acc[u][v]);
        }
        __syncthreads();
    }

    float lmin =  3.402823466e+38f;
    float lmax = -3.402823466e+38f;
    #pragma unroll
    for (int u = 0; u < 4; ++u){
        int i = i0 + ty*4 + u;
        if (i >= Mz) continue;
        #pragma unroll
        for (int v = 0; v < 4; ++v){
            int j = j0 + tx*4 + v;
            if (j >= Nz) continue;
            float r;
            if (EPI == 0){
                r = 1.0f - acc[u][v];
                lmin = fminf(lmin, r);
                lmax = fmaxf(lmax, r);
            } else if (EPI == 1){
                r = acc[u][v];
            } else {
                r = rowadd[b*Mz + i] + coladd[b*Nz + j] - 2.0f*acc[u][v];
            }
            Cp[(size_t)i*Nz + j] = r;
        }
    }
    if (EPI == 0){
        #pragma unroll
        for (int o = 16; o; o >>= 1){
            lmin = fminf(lmin, __shfl_xor_sync(0xffffffffu, lmin, o));
            lmax = fmaxf(lmax, __shfl_xor_sync(0xffffffffu, lmax, o));
        }
        if ((tid & 31) == 0){
            atomicMin(&g_minmax[2*mmIdx],   enc_mono(lmin));
            atomicMax(&g_minmax[2*mmIdx+1], enc_mono(lmax));
        }
    }
}

// ---------------- global-threshold ReLU (+ optional int mask -> 1.0 / 1e-5) ----------------
__global__ void thresh_kernel(float* __restrict__ Carr, const int* __restrict__ maskArr,
                              int total, int pairIdx)
{
    const float mn = dec_mono(g_minmax[2*pairIdx]);
    const float mx = dec_mono(g_minmax[2*pairIdx+1]);
    const float thr = mn + 0.1f*(mx - mn);
    for (int e = blockIdx.x*blockDim.x + threadIdx.x; e < total; e += gridDim.x*blockDim.x){
        float v = Carr[e] - thr;
        v = v > 0.f ? v : 0.f;
        if (maskArr) v *= (maskArr[e] == 1 ? 1.0f : 1e-5f);
        Carr[e] = v;
    }
}

// ---------------- row mean of squares: out[bp] = mean_k A[bp][k]^2 ----------------
__global__ void rowmeansq_kernel(const float* __restrict__ A, float* __restrict__ outp, int rowlen)
{
    const float* r = A + (size_t)blockIdx.x * rowlen;
    float ss = 0.f;
    for (int k = threadIdx.x; k < rowlen; k += blockDim.x){
        float t = r[k]; ss += t*t;
    }
    #pragma unroll
    for (int o = 16; o; o >>= 1) ss += __shfl_xor_sync(0xffffffffu, ss, o);
    __shared__ float sred[8];
    if ((threadIdx.x & 31) == 0) sred[threadIdx.x >> 5] = ss;
    __syncthreads();
    if (threadIdx.x == 0){
        float t = 0.f;
        for (int w = 0; w < 8; ++w) t += sred[w];
        outp[blockIdx.x] = t / (float)rowlen;
    }
}

__global__ void fill_kernel(float* __restrict__ p, float val, int total){
    for (int e = blockIdx.x*blockDim.x + threadIdx.x; e < total; e += gridDim.x*blockDim.x)
        p[e] = val;
}

// ---------------- IPOT: one persistent 1024-thread CTA per batch ----------------
// Thread layout: j = tid&255 (column), rq = tid>>8; rows i = rq + 4k, k=0..48.
// E = exp(-2C) in dynamic smem (200704 B). T resident in registers (49/thread).
__global__ void __launch_bounds__(1024, 1)
ipot_kernel(const float* __restrict__ Cmat, float* __restrict__ Tout,
            float* __restrict__ dotOut)
{
    extern __shared__ float sE[];
    const int tid  = threadIdx.x;
    const int j    = tid & 255;
    const int rq   = tid >> 8;
    const int lane = tid & 31;
    const int wid  = tid >> 5;
    const int b    = blockIdx.x;
    const float* C = Cmat + (size_t)b * NM;

    __shared__ float s_sigma[256];
    __shared__ float s_delta[196];
    __shared__ float s_part[32][49];
    __shared__ float s_col[4][256];
    __shared__ float s_dred[32];

    float T[49];
    #pragma unroll
    for (int k = 0; k < 49; ++k){
        float c = C[tid + 1024*k];
        sE[tid + 1024*k] = expf(-2.0f*c);   // A = exp(-C/beta), beta=0.5
        T[k] = 1.0f;
    }
    if (tid < 256) s_sigma[tid] = 1.0f/256.0f;
    __syncthreads();

    for (int it = 0; it < 20; ++it){
        // pass1: row sums of Q*sigma (Q = E*T), warp butterfly over 32 columns
        const float sig = s_sigma[j];
        #pragma unroll
        for (int k = 0; k < 49; ++k){
            float v = sE[tid + 1024*k]*T[k]*sig;
            v += __shfl_xor_sync(0xffffffffu, v, 16);
            v += __shfl_xor_sync(0xffffffffu, v, 8);
            v += __shfl_xor_sync(0xffffffffu, v, 4);
            v += __shfl_xor_sync(0xffffffffu, v, 2);
            v += __shfl_xor_sync(0xffffffffu, v, 1);
            if (lane == 0) s_part[wid][k] = v;
        }
        __syncthreads();
        if (tid < 196){
            int r2 = tid & 3, k2 = tid >> 2;     // row i = r2 + 4*k2
            float s = 0.f;
            #pragma unroll
            for (int w = 0; w < 8; ++w) s += s_part[r2*8 + w][k2];
            s_delta[tid] = 1.0f / (196.0f * s);
        }
        __syncthreads();
        // pass2: column sums of Q*delta (thread-local over its 49 rows)
        float cs = 0.f;
        #pragma unroll
        for (int k = 0; k < 49; ++k)
            cs += sE[tid + 1024*k]*T[k]*s_delta[rq + 4*k];
        s_col[rq][j] = cs;
        __syncthreads();
        if (tid < 256){
            float c = s_col[0][tid] + s_col[1][tid] + s_col[2][tid] + s_col[3][tid];
            s_sigma[tid] = 1.0f / (256.0f * c);
        }
        __syncthreads();
        // pass3: T = delta * Q * sigma
        const float sg = s_sigma[j];
        #pragma unroll
        for (int k = 0; k < 49; ++k)
            T[k] = s_delta[rq + 4*k] * sE[tid + 1024*k] * T[k] * sg;
    }

    const size_t base = (size_t)b * NM;
    #pragma unroll
    for (int k = 0; k < 49; ++k)
        Tout[base + tid + 1024*k] = T[k];

    if (dotOut){
        float dot = 0.f;
        #pragma unroll
        for (int k = 0; k < 49; ++k)
            dot += C[tid + 1024*k] * T[k];
        #pragma unroll
        for (int o = 16; o; o >>= 1) dot += __shfl_xor_sync(0xffffffffu, dot, o);
        if (lane == 0) s_dred[wid] = dot;
        __syncthreads();
        if (tid == 0){
            float t = 0.f;
            for (int w = 0; w < 32; ++w) t += s_dred[w];
            dotOut[b] = t;
        }
    }
}

// ---------------- per-batch dot: out[b] = sum(A[b]*B[b]) ----------------
__global__ void dotmul_kernel(const float* __restrict__ A, const float* __restrict__ Bv,
                              float* __restrict__ outp)
{
    const int b = blockIdx.x;
    const size_t base = (size_t)b * NM;
    float s = 0.f;
    for (int e = threadIdx.x; e < NM; e += blockDim.x)
        s += A[base + e] * Bv[base + e];
    #pragma unroll
    for (int o = 16; o; o >>= 1) s += __shfl_xor_sync(0xffffffffu, s, o);
    __shared__ float sred[8];
    if ((threadIdx.x & 31) == 0) sred[threadIdx.x >> 5] = s;
    __syncthreads();
    if (threadIdx.x == 0){
        float t = 0.f;
        for (int w = 0; w < 8; ++w) t += sred[w];
        outp[b] = t;
    }
}

__global__ void copy_kernel(float* __restrict__ dst, const float* __restrict__ src, int total){
    for (int e = blockIdx.x*blockDim.x + threadIdx.x; e < total; e += gridDim.x*blockDim.x)
        dst[e] = src[e];
}

// twd = 0.1*mean(gwd) + 0.1*mean(wd), wd_b = -dotwd_b, gwd_b = dotgw_b
__global__ void final_kernel(float* __restrict__ outp){
    int t = threadIdx.x;
    float wd = g_dotwd[t];
    float gw = g_dotgw[t];
    #pragma unroll
    for (int o = 16; o; o >>= 1){
        wd += __shfl_xor_sync(0xffffffffu, wd, o);
        gw += __shfl_xor_sync(0xffffffffu, gw, o);
    }
    if (t == 0)
        outp[0] = 0.1f*(gw * (1.0f/B_)) - 0.1f*(wd * (1.0f/B_));
}

// ---------------- host launcher ----------------
extern "C" void kernel_launch(void* const* d_in, const int* in_sizes, int n_in,
                              void* d_out, int out_size)
{
    const float* img     = (const float*)d_in[0];  // (32,196,1024)
    const float* tok     = (const float*)d_in[1];  // (32,256,1024)
    const float* tokmask = (const float*)d_in[2];  // (32,256)
    const int*   tdm     = (const int*)d_in[3];    // (32,256,256)
    const int*   irm     = (const int*)d_in[4];    // (32,196,196)
    float* out = (float*)d_out;                    // [1 | T_wd | T_gwd]

    float *xn, *yn, *Cxy, *Cs, *Ct, *gam, *tmp, *Cg, *crow, *ccol, *dwd, *dgw;
    cudaGetSymbolAddress((void**)&xn,  g_xn);
    cudaGetSymbolAddress((void**)&yn,  g_yn);
    cudaGetSymbolAddress((void**)&Cxy, g_Cxy);
    cudaGetSymbolAddress((void**)&Cs,  g_Cs);
    cudaGetSymbolAddress((void**)&Ct,  g_Ct);
    cudaGetSymbolAddress((void**)&gam, g_gamma);
    cudaGetSymbolAddress((void**)&tmp, g_tmp);
    cudaGetSymbolAddress((void**)&Cg,  g_Cg);
    cudaGetSymbolAddress((void**)&crow, g_cstrow);
    cudaGetSymbolAddress((void**)&ccol, g_cstcol);
    cudaGetSymbolAddress((void**)&dwd, g_dotwd);
    cudaGetSymbolAddress((void**)&dgw, g_dotgw);

    cudaFuncSetAttribute(ipot_kernel, cudaFuncAttributeMaxDynamicSharedMemorySize, NM*(int)sizeof(float));

    init_kernel<<<1, 64>>>();
    normalize_kernel<<<B_*N_IMG, 256>>>(img, nullptr, xn, N_IMG);
    normalize_kernel<<<B_*M_TOK, 256>>>(tok, tokmask, yn, M_TOK);

    // cosine cost matrices (epilogue 1-acc + global min/max)
    gemm_kernel<0,0><<<dim3(4,4,B_), 256>>>(xn, yn, Cxy, N_IMG, M_TOK, D_, nullptr, nullptr, 0);
    gemm_kernel<0,0><<<dim3(4,4,B_), 256>>>(xn, xn, Cs,  N_IMG, N_IMG, D_, nullptr, nullptr, 1);
    gemm_kernel<0,0><<<dim3(4,4,B_), 256>>>(yn, yn, Ct,  M_TOK, M_TOK, D_, nullptr, nullptr, 2);

    thresh_kernel<<<1024, 256>>>(Cxy, nullptr, B_*NM, 0);
    thresh_kernel<<<1024, 256>>>(Cs,  irm, B_*N_IMG*N_IMG, 1);
    thresh_kernel<<<1024, 256>>>(Ct,  tdm, B_*M_TOK*M_TOK, 2);

    // Wasserstein: IPOT on Cxy -> T_wd (written directly into output) + dot
    ipot_kernel<<<B_, 1024, NM*(int)sizeof(float)>>>(Cxy, out + 1, dwd);

    // Gromov-Wasserstein setup
    rowmeansq_kernel<<<B_*N_IMG, 256>>>(Cs, crow, N_IMG);
    rowmeansq_kernel<<<B_*M_TOK, 256>>>(Ct, ccol, M_TOK);
    fill_kernel<<<512, 256>>>(gam, 1.0f/(float)NM, B_*NM);

    for (int it = 0; it < 6; ++it){
        // tmp = Cs @ gamma    (196x196 @ 196x256, B row-major [K][N])
        gemm_kernel<1,1><<<dim3(4,4,B_), 256>>>(Cs, gam, tmp, N_IMG, M_TOK, N_IMG, nullptr, nullptr, 0);
        // Cg = Cst - 2 * tmp @ Ct^T
        gemm_kernel<0,2><<<dim3(4,4,B_), 256>>>(tmp, Ct, Cg, N_IMG, M_TOK, M_TOK, crow, ccol, 0);
        if (it < 5)
            ipot_kernel<<<B_, 1024, NM*(int)sizeof(float)>>>(Cg, gam, nullptr);
    }

    dotmul_kernel<<<B_, 256>>>(Cg, gam, dgw);
    copy_kernel<<<512, 256>>>(out + 1 + (size_t)B_*NM, gam, B_*NM);
    final_kernel<<<1, 32>>>(out);
}

// round 4
// speedup vs baseline: 2.2197x; 2.2197x over previous
#include <cuda_runtime.h>
#include <cuda_bf16.h>
#include <cooperative_groups.h>
#include <math.h>

namespace cg = cooperative_groups;

#define B_    32
#define N_IMG 196
#define M_TOK 256
#define D_    1024
#define NM    (N_IMG*M_TOK)

// ---------------- device scratch (allocation-free) ----------------
__device__ __nv_bfloat16 g_xh[B_*N_IMG*D_];
__device__ __nv_bfloat16 g_xl[B_*N_IMG*D_];
__device__ __nv_bfloat16 g_yh[B_*M_TOK*D_];
__device__ __nv_bfloat16 g_yl[B_*M_TOK*D_];
__device__ float g_Cxy[B_*NM];
__device__ float g_Cs [B_*N_IMG*N_IMG];
__device__ float g_Ct [B_*M_TOK*M_TOK];
__device__ float g_gamma[B_*NM];
__device__ float g_tmp  [B_*NM];
__device__ float g_Cg   [B_*NM];
__device__ float g_cstrow[B_*N_IMG];
__device__ float g_cstcol[B_*M_TOK];
__device__ unsigned g_minmax[6];
__device__ float g_dotwd[B_];
__device__ float g_dotgw[B_];

// order-preserving float<->uint encoding
__device__ __forceinline__ unsigned enc_mono(float f){
    unsigned u = __float_as_uint(f);
    return (u & 0x80000000u) ? ~u : (u | 0x80000000u);
}
__device__ __forceinline__ float dec_mono(unsigned e){
    unsigned u = (e & 0x80000000u) ? (e ^ 0x80000000u) : ~e;
    return __uint_as_float(u);
}

__device__ __forceinline__ uint32_t smem_u32(const void* p){
    uint32_t a;
    asm("{ .reg .u64 t; cvta.to.shared.u64 t, %1; cvt.u32.u64 %0, t; }" : "=r"(a) : "l"(p));
    return a;
}

// ldmatrix (baseline PTX, sm_75+)
__device__ __forceinline__ void ldm_x4(unsigned* r, uint32_t addr){
    asm volatile("ldmatrix.sync.aligned.m8n8.x4.shared.b16 {%0,%1,%2,%3}, [%4];"
        : "=r"(r[0]), "=r"(r[1]), "=r"(r[2]), "=r"(r[3]) : "r"(addr));
}
// mma bf16 (baseline PTX, sm_80+)
__device__ __forceinline__ void mma_bf16(float* d, const unsigned* a, unsigned b0, unsigned b1){
    asm volatile("mma.sync.aligned.m16n8k16.row.col.f32.bf16.bf16.f32 "
        "{%0,%1,%2,%3}, {%4,%5,%6,%7}, {%8,%9}, {%0,%1,%2,%3};"
        : "+f"(d[0]), "+f"(d[1]), "+f"(d[2]), "+f"(d[3])
        : "r"(a[0]), "r"(a[1]), "r"(a[2]), "r"(a[3]), "r"(b0), "r"(b1));
}

// ---------------- init ----------------
__global__ void init_kernel(){
    int t = threadIdx.x;
    if (t < 3){ g_minmax[2*t] = 0xFFFFFFFFu; g_minmax[2*t+1] = 0u; }
}

// ---------------- normalize: L2 over D, emit bf16 hi/lo split ----------------
__global__ void normalize_kernel(const float* __restrict__ x,
                                 const float* __restrict__ mask,
                                 __nv_bfloat16* __restrict__ oh,
                                 __nv_bfloat16* __restrict__ ol, int npos)
{
    const int bp  = blockIdx.x;
    const int b   = bp / npos;
    const int pos = bp - b*npos;
    const float* v = x + (size_t)bp * D_;
    const float mk = mask ? mask[(size_t)b*npos + pos] : 1.0f;

    float ss = 0.f;
    for (int d = threadIdx.x; d < D_; d += blockDim.x){
        float t = v[d] * mk;
        ss += t*t;
    }
    #pragma unroll
    for (int o = 16; o; o >>= 1) ss += __shfl_xor_sync(0xffffffffu, ss, o);
    __shared__ float sred[8];
    if ((threadIdx.x & 31) == 0) sred[threadIdx.x >> 5] = ss;
    __syncthreads();
    __shared__ float s_inv;
    if (threadIdx.x == 0){
        float t = 0.f;
        for (int w = 0; w < 8; ++w) t += sred[w];
        s_inv = 1.0f / (sqrtf(t) + 1e-12f);
    }
    __syncthreads();
    const float scale = s_inv * mk;
    const size_t base = (size_t)bp * D_;
    for (int d = threadIdx.x; d < D_; d += blockDim.x){
        float t = v[d] * scale;
        __nv_bfloat16 hi = __float2bfloat16(t);
        __nv_bfloat16 lo = __float2bfloat16(t - __bfloat162float(hi));
        oh[base + d] = hi;
        ol[base + d] = lo;
    }
}

// ---------------- cosine GEMM via mma.sync bf16 hi/lo split ----------------
// C[b][i][j] = 1 - dot(X[i], Y[j]) = 1 - (hh + hl + lh). Global min/max tracked.
// CTA tile 64(M) x 128(N); 8 warps in 2x4; warp tile 32x32; K-chunk 32.
#define LDT 40   // smem row stride (bf16): 80B = 5x16B, conflict-free, 16B aligned

__global__ void __launch_bounds__(256,1)
cosmma_kernel(const __nv_bfloat16* __restrict__ Ah, const __nv_bfloat16* __restrict__ Al,
              const __nv_bfloat16* __restrict__ Bh, const __nv_bfloat16* __restrict__ Bl,
              float* __restrict__ Cout, int Mz, int Nz, int mmIdx)
{
    __shared__ __align__(16) __nv_bfloat16 sAh[64][LDT];
    __shared__ __align__(16) __nv_bfloat16 sAl[64][LDT];
    __shared__ __align__(16) __nv_bfloat16 sBh[128][LDT];
    __shared__ __align__(16) __nv_bfloat16 sBl[128][LDT];

    const int tid  = threadIdx.x;
    const int lane = tid & 31;
    const int wid  = tid >> 5;
    const int wm   = wid >> 2;           // 0..1
    const int wn   = wid & 3;            // 0..3
    const int b    = blockIdx.z;
    const int m0   = blockIdx.y * 64;
    const int j0   = blockIdx.x * 128;

    const size_t abase = (size_t)b * Mz * D_;
    const size_t bbase = (size_t)b * Nz * D_;

    // loader indices
    const int a_row = tid >> 2, a_quad = tid & 3;
    const bool avalid = (m0 + a_row) < Mz;
    const uint4 zero4 = make_uint4(0,0,0,0);

    // ldmatrix lane addressing pieces
    const uint32_t baAh = smem_u32(&sAh[0][0]);
    const uint32_t baAl = smem_u32(&sAl[0][0]);
    const uint32_t baBh = smem_u32(&sBh[0][0]);
    const uint32_t baBl = smem_u32(&sBl[0][0]);
    const int arow_l = lane & 15, ahalf = lane >> 4;
    const int bg = lane >> 3;
    const int b_noff = ((bg >> 1) << 3) + (lane & 7);
    const int b_koff = (bg & 1) << 3;

    float acc[2][4][4];
    #pragma unroll
    for (int mt = 0; mt < 2; ++mt)
        #pragma unroll
        for (int nt = 0; nt < 4; ++nt)
            #pragma unroll
            for (int q = 0; q < 4; ++q) acc[mt][nt][q] = 0.f;

    for (int kc = 0; kc < 32; ++kc){
        // ---- load A (64 x 32 bf16, hi & lo) ----
        {
            const size_t go = abase + (size_t)(m0 + a_row) * D_ + kc*32 + a_quad*8;
            uint4 vh = zero4, vl = zero4;
            if (avalid){
                vh = *reinterpret_cast<const uint4*>(Ah + go);
                vl = *reinterpret_cast<const uint4*>(Al + go);
            }
            *reinterpret_cast<uint4*>(&sAh[a_row][a_quad*8]) = vh;
            *reinterpret_cast<uint4*>(&sAl[a_row][a_quad*8]) = vl;
        }
        // ---- load B (128 x 32 bf16, hi & lo) ----
        #pragma unroll
        for (int p = 0; p < 2; ++p){
            int idx = tid + p*256;
            int row = idx >> 2, quad = idx & 3;
            const bool bvalid = (j0 + row) < Nz;
            const size_t go = bbase + (size_t)(j0 + row) * D_ + kc*32 + quad*8;
            uint4 vh = zero4, vl = zero4;
            if (bvalid){
                vh = *reinterpret_cast<const uint4*>(Bh + go);
                vl = *reinterpret_cast<const uint4*>(Bl + go);
            }
            *reinterpret_cast<uint4*>(&sBh[row][quad*8]) = vh;
            *reinterpret_cast<uint4*>(&sBl[row][quad*8]) = vl;
        }
        __syncthreads();

        #pragma unroll
        for (int k16 = 0; k16 < 2; ++k16){
            unsigned ah[2][4], al[2][4], bh[2][4], bl[2][4];
            #pragma unroll
            for (int mt = 0; mt < 2; ++mt){
                uint32_t off = (uint32_t)(((wm*32 + mt*16 + arow_l)*LDT + k16*16 + ahalf*8) * 2);
                ldm_x4(ah[mt], baAh + off);
                ldm_x4(al[mt], baAl + off);
            }
            #pragma unroll
            for (int nt2 = 0; nt2 < 2; ++nt2){
                uint32_t off = (uint32_t)(((wn*32 + nt2*16 + b_noff)*LDT + k16*16 + b_koff) * 2);
                ldm_x4(bh[nt2], baBh + off);
                ldm_x4(bl[nt2], baBl + off);
            }
            #pragma unroll
            for (int mt = 0; mt < 2; ++mt)
                #pragma unroll
                for (int nt = 0; nt < 4; ++nt){
                    const int p2 = nt >> 1, s2 = (nt & 1) * 2;
                    mma_bf16(acc[mt][nt], ah[mt], bh[p2][s2], bh[p2][s2+1]);
                    mma_bf16(acc[mt][nt], ah[mt], bl[p2][s2], bl[p2][s2+1]);
                    mma_bf16(acc[mt][nt], al[mt], bh[p2][s2], bh[p2][s2+1]);
                }
        }
        __syncthreads();
    }

    // ---- epilogue: 1 - acc, store, global min/max ----
    float lmin =  3.402823466e+38f;
    float lmax = -3.402823466e+38f;
    #pragma unroll
    for (int mt = 0; mt < 2; ++mt){
        #pragma unroll
        for (int nt = 0; nt < 4; ++nt){
            const int ibase = m0 + wm*32 + mt*16 + (lane >> 2);
            const int jbase = j0 + wn*32 + nt*8 + (lane & 3)*2;
            #pragma unroll
            for (int rr = 0; rr < 2; ++rr){
                int i = ibase + rr*8;
                if (i >= Mz) continue;
                float* crow = Cout + ((size_t)b*Mz + i)*Nz;
                #pragma unroll
                for (int cc = 0; cc < 2; ++cc){
                    int j = jbase + cc;
                    if (j >= Nz) continue;
                    float v = 1.0f - acc[mt][nt][rr*2 + cc];
                    crow[j] = v;
                    lmin = fminf(lmin, v);
                    lmax = fmaxf(lmax, v);
                }
            }
        }
    }
    #pragma unroll
    for (int o = 16; o; o >>= 1){
        lmin = fminf(lmin, __shfl_xor_sync(0xffffffffu, lmin, o));
        lmax = fmaxf(lmax, __shfl_xor_sync(0xffffffffu, lmax, o));
    }
    if (lane == 0){
        atomicMin(&g_minmax[2*mmIdx],   enc_mono(lmin));
        atomicMax(&g_minmax[2*mmIdx+1], enc_mono(lmax));
    }
}

// ---------------- SIMT GEMM for the GW chain ----------------
template<int BLAYOUT, int EPI>
__global__ void __launch_bounds__(256)
gemm_kernel(const float* __restrict__ Aall, const float* __restrict__ Ball,
            float* __restrict__ Call, int Mz, int Nz, int Kz,
            const float* __restrict__ rowadd, const float* __restrict__ coladd)
{
    const int b = blockIdx.z;
    const float* A  = Aall + (size_t)b * Mz * Kz;
    const float* Bp = Ball + (size_t)b * Nz * Kz;
    float* Cp       = Call + (size_t)b * Mz * Nz;
    const int i0 = blockIdx.y * 64, j0 = blockIdx.x * 64;

    __shared__ __align__(16) float As[16][68];
    __shared__ __align__(16) float Bs[16][68];

    const int tid = threadIdx.x;
    const int tx = tid & 15, ty = tid >> 4;
    float acc[4][4];
    #pragma unroll
    for (int u = 0; u < 4; ++u)
        #pragma unroll
        for (int v = 0; v < 4; ++v) acc[u][v] = 0.f;

    for (int k0 = 0; k0 < Kz; k0 += 16){
        #pragma unroll
        for (int p = 0; p < 4; ++p){
            int idx = tid + p*256;
            int kk = idx & 15, ii = idx >> 4;
            float v = 0.f;
            if (i0+ii < Mz && k0+kk < Kz) v = A[(size_t)(i0+ii)*Kz + (k0+kk)];
            As[kk][ii] = v;
        }
        if (BLAYOUT == 0){
            #pragma unroll
            for (int p = 0; p < 4; ++p){
                int idx = tid + p*256;
                int kk = idx & 15, jj = idx >> 4;
                float v = 0.f;
                if (j0+jj < Nz && k0+kk < Kz) v = Bp[(size_t)(j0+jj)*Kz + (k0+kk)];
                Bs[kk][jj] = v;
            }
        } else {
            #pragma unroll
            for (int p = 0; p < 4; ++p){
                int idx = tid + p*256;
                int jj = idx & 63, kk = idx >> 6;
                float v = 0.f;
                if (k0+kk < Kz && j0+jj < Nz) v = Bp[(size_t)(k0+kk)*Nz + (j0+jj)];
                Bs[kk][jj] = v;
            }
        }
        __syncthreads();
        #pragma unroll
        for (int kk = 0; kk < 16; ++kk){
            float4 a4 = *(const float4*)&As[kk][ty*4];
            float4 b4 = *(const float4*)&Bs[kk][tx*4];
            float a[4]  = {a4.x, a4.y, a4.z, a4.w};
            float bb[4] = {b4.x, b4.y, b4.z, b4.w};
            #pragma unroll
            for (int u = 0; u < 4; ++u)
                #pragma unroll
                for (int v = 0; v < 4; ++v)
                    acc[u][v] = fmaf(a[u], bb[v], acc[u][v]);
        }
        __syncthreads();
    }

    #pragma unroll
    for (int u = 0; u < 4; ++u){
        int i = i0 + ty*4 + u;
        if (i >= Mz) continue;
        #pragma unroll
        for (int v = 0; v < 4; ++v){
            int j = j0 + tx*4 + v;
            if (j >= Nz) continue;
            float r;
            if (EPI == 1){
                r = acc[u][v];
            } else {
                r = rowadd[b*Mz + i] + coladd[b*Nz + j] - 2.0f*acc[u][v];
            }
            Cp[(size_t)i*Nz + j] = r;
        }
    }
}

// ---------------- threshold ReLU ----------------
__global__ void thresh_kernel(float* __restrict__ Carr, const int* __restrict__ maskArr,
                              int total, int pairIdx)
{
    const float mn = dec_mono(g_minmax[2*pairIdx]);
    const float mx = dec_mono(g_minmax[2*pairIdx+1]);
    const float thr = mn + 0.1f*(mx - mn);
    for (int e = blockIdx.x*blockDim.x + threadIdx.x; e < total; e += gridDim.x*blockDim.x){
        float v = Carr[e] - thr;
        v = v > 0.f ? v : 0.f;
        if (maskArr) v *= (maskArr[e] == 1 ? 1.0f : 1e-5f);
        Carr[e] = v;
    }
}

__global__ void rowmeansq_kernel(const float* __restrict__ A, float* __restrict__ outp, int rowlen)
{
    const float* r = A + (size_t)blockIdx.x * rowlen;
    float ss = 0.f;
    for (int k = threadIdx.x; k < rowlen; k += blockDim.x){
        float t = r[k]; ss += t*t;
    }
    #pragma unroll
    for (int o = 16; o; o >>= 1) ss += __shfl_xor_sync(0xffffffffu, ss, o);
    __shared__ float sred[8];
    if ((threadIdx.x & 31) == 0) sred[threadIdx.x >> 5] = ss;
    __syncthreads();
    if (threadIdx.x == 0){
        float t = 0.f;
        for (int w = 0; w < 8; ++w) t += sred[w];
        outp[blockIdx.x] = t / (float)rowlen;
    }
}

__global__ void fill_kernel(float* __restrict__ p, float val, int total){
    for (int e = blockIdx.x*blockDim.x + threadIdx.x; e < total; e += gridDim.x*blockDim.x)
        p[e] = val;
}

// ---------------- IPOT: 4-CTA cluster per batch, E & T register-resident ----------------
__global__ void __cluster_dims__(4,1,1) __launch_bounds__(256,1)
ipot_kernel(const float* __restrict__ Cmat, float* __restrict__ Tout,
            float* __restrict__ dotOut)
{
    cg::cluster_group cluster = cg::this_cluster();
    const int rank = blockIdx.x;
    const int b    = blockIdx.y;
    const int tid  = threadIdx.x;
    const int jl   = tid & 63;
    const int rq   = tid >> 6;
    const int lane = tid & 31;
    const int wid  = tid >> 5;
    const int jg   = rank*64 + jl;
    const float* C = Cmat + (size_t)b * NM;

    __shared__ float s_sigma[64];
    __shared__ float s_delta[196];
    __shared__ float s_part[8][49];
    __shared__ float s_rowpart[2][196];
    __shared__ float s_col[4][64];
    __shared__ float s_dred[8];
    __shared__ float s_dotpart;

    float E[49], T[49];
    #pragma unroll
    for (int k = 0; k < 49; ++k){
        float c = C[(rq + 4*k)*M_TOK + jg];
        E[k] = expf(-2.0f * c);
        T[k] = 1.0f;
    }
    if (tid < 64) s_sigma[tid] = 1.0f/256.0f;
    __syncthreads();

    for (int it = 0; it < 20; ++it){
        const int buf = it & 1;
        const float sig = s_sigma[jl];
        #pragma unroll
        for (int k = 0; k < 49; ++k){
            float v = E[k]*T[k]*sig;
            v += __shfl_xor_sync(0xffffffffu, v, 16);
            v += __shfl_xor_sync(0xffffffffu, v, 8);
            v += __shfl_xor_sync(0xffffffffu, v, 4);
            v += __shfl_xor_sync(0xffffffffu, v, 2);
            v += __shfl_xor_sync(0xffffffffu, v, 1);
            if (lane == 0) s_part[wid][k] = v;
        }
        __syncthreads();
        if (tid < 196){
            int r2 = tid & 3, k2 = tid >> 2;
            s_rowpart[buf][tid] = s_part[r2*2][k2] + s_part[r2*2+1][k2];
        }
        cluster.sync();
        if (tid < 196){
            float s = 0.f;
            #pragma unroll
            for (int r = 0; r < 4; ++r)
                s += *(cluster.map_shared_rank(&s_rowpart[buf][0], r) + tid);
            s_delta[tid] = 1.0f / (196.0f * s);
        }
        __syncthreads();
        float cs = 0.f;
        #pragma unroll
        for (int k = 0; k < 49; ++k)
            cs += E[k]*T[k]*s_delta[rq + 4*k];
        s_col[rq][jl] = cs;
        __syncthreads();
        if (tid < 64){
            float c = s_col[0][tid] + s_col[1][tid] + s_col[2][tid] + s_col[3][tid];
            s_sigma[tid] = 1.0f / (256.0f * c);
        }
        __syncthreads();
        const float sg = s_sigma[jl];
        #pragma unroll
        for (int k = 0; k < 49; ++k)
            T[k] = s_delta[rq + 4*k] * E[k] * T[k] * sg;
    }

    const size_t base = (size_t)b * NM;
    #pragma unroll
    for (int k = 0; k < 49; ++k)
        Tout[base + (size_t)(rq + 4*k)*M_TOK + jg] = T[k];

    if (dotOut){
        float dot = 0.f;
        #pragma unroll
        for (int k = 0; k < 49; ++k)
            dot += C[(rq + 4*k)*M_TOK + jg] * T[k];
        #pragma unroll
        for (int o = 16; o; o >>= 1) dot += __shfl_xor_sync(0xffffffffu, dot, o);
        if (lane == 0) s_dred[wid] = dot;
        __syncthreads();
        if (tid == 0){
            float t = 0.f;
            for (int w = 0; w < 8; ++w) t += s_dred[w];
            s_dotpart = t;
        }
        cluster.sync();
        if (rank == 0 && tid == 0){
            float t = 0.f;
            #pragma unroll
            for (int r = 0; r < 4; ++r)
                t += *cluster.map_shared_rank(&s_dotpart, r);
            dotOut[b] = t;
        }
    }
    cluster.sync();
}

// ---------------- per-batch dot ----------------
__global__ void dotmul_kernel(const float* __restrict__ A, const float* __restrict__ Bv,
                              float* __restrict__ outp)
{
    const int b = blockIdx.x;
    const size_t base = (size_t)b * NM;
    float s = 0.f;
    for (int e = threadIdx.x; e < NM; e += blockDim.x)
        s += A[base + e] * Bv[base + e];
    #pragma unroll
    for (int o = 16; o; o >>= 1) s += __shfl_xor_sync(0xffffffffu, s, o);
    __shared__ float sred[8];
    if ((threadIdx.x & 31) == 0) sred[threadIdx.x >> 5] = s;
    __syncthreads();
    if (threadIdx.x == 0){
        float t = 0.f;
        for (int w = 0; w < 8; ++w) t += sred[w];
        outp[b] = t;
    }
}

__global__ void copy_kernel(float* __restrict__ dst, const float* __restrict__ src, int total){
    for (int e = blockIdx.x*blockDim.x + threadIdx.x; e < total; e += gridDim.x*blockDim.x)
        dst[e] = src[e];
}

__global__ void final_kernel(float* __restrict__ outp){
    int t = threadIdx.x;
    float wd = g_dotwd[t];
    float gw = g_dotgw[t];
    #pragma unroll
    for (int o = 16; o; o >>= 1){
        wd += __shfl_xor_sync(0xffffffffu, wd, o);
        gw += __shfl_xor_sync(0xffffffffu, gw, o);
    }
    if (t == 0)
        outp[0] = 0.1f*(gw * (1.0f/B_)) - 0.1f*(wd * (1.0f/B_));
}

// ---------------- host launcher ----------------
extern "C" void kernel_launch(void* const* d_in, const int* in_sizes, int n_in,
                              void* d_out, int out_size)
{
    const float* img     = (const float*)d_in[0];
    const float* tok     = (const float*)d_in[1];
    const float* tokmask = (const float*)d_in[2];
    const int*   tdm     = (const int*)d_in[3];
    const int*   irm     = (const int*)d_in[4];
    float* out = (float*)d_out;                    // [1 | T_wd | T_gwd]

    __nv_bfloat16 *xh, *xl, *yh, *yl;
    float *Cxy, *Cs, *Ct, *gam, *tmp, *Cg, *crow, *ccol, *dwd, *dgw;
    cudaGetSymbolAddress((void**)&xh,  g_xh);
    cudaGetSymbolAddress((void**)&xl,  g_xl);
    cudaGetSymbolAddress((void**)&yh,  g_yh);
    cudaGetSymbolAddress((void**)&yl,  g_yl);
    cudaGetSymbolAddress((void**)&Cxy, g_Cxy);
    cudaGetSymbolAddress((void**)&Cs,  g_Cs);
    cudaGetSymbolAddress((void**)&Ct,  g_Ct);
    cudaGetSymbolAddress((void**)&gam, g_gamma);
    cudaGetSymbolAddress((void**)&tmp, g_tmp);
    cudaGetSymbolAddress((void**)&Cg,  g_Cg);
    cudaGetSymbolAddress((void**)&crow, g_cstrow);
    cudaGetSymbolAddress((void**)&ccol, g_cstcol);
    cudaGetSymbolAddress((void**)&dwd, g_dotwd);
    cudaGetSymbolAddress((void**)&dgw, g_dotgw);

    init_kernel<<<1, 64>>>();
    normalize_kernel<<<B_*N_IMG, 256>>>(img, nullptr, xh, xl, N_IMG);
    normalize_kernel<<<B_*M_TOK, 256>>>(tok, tokmask, yh, yl, M_TOK);

    // cosine cost matrices on tensor cores (mma.sync bf16-split, fp32 accumulate)
    cosmma_kernel<<<dim3(2,4,B_), 256>>>(xh, xl, yh, yl, Cxy, N_IMG, M_TOK, 0);
    cosmma_kernel<<<dim3(2,4,B_), 256>>>(xh, xl, xh, xl, Cs,  N_IMG, N_IMG, 1);
    cosmma_kernel<<<dim3(2,4,B_), 256>>>(yh, yl, yh, yl, Ct,  M_TOK, M_TOK, 2);

    thresh_kernel<<<1024, 256>>>(Cxy, nullptr, B_*NM, 0);
    thresh_kernel<<<1024, 256>>>(Cs,  irm, B_*N_IMG*N_IMG, 1);
    thresh_kernel<<<1024, 256>>>(Ct,  tdm, B_*M_TOK*M_TOK, 2);

    // Wasserstein IPOT -> T_wd (direct to output) + per-batch dot
    ipot_kernel<<<dim3(4,B_), 256>>>(Cxy, out + 1, dwd);

    // GW setup
    rowmeansq_kernel<<<B_*N_IMG, 256>>>(Cs, crow, N_IMG);
    rowmeansq_kernel<<<B_*M_TOK, 256>>>(Ct, ccol, M_TOK);
    fill_kernel<<<512, 256>>>(gam, 1.0f/(float)NM, B_*NM);

    for (int it = 0; it < 6; ++it){
        gemm_kernel<1,1><<<dim3(4,4,B_), 256>>>(Cs, gam, tmp, N_IMG, M_TOK, N_IMG, nullptr, nullptr);
        gemm_kernel<0,2><<<dim3(4,4,B_), 256>>>(tmp, Ct, Cg, N_IMG, M_TOK, M_TOK, crow, ccol);
        if (it < 5)
            ipot_kernel<<<dim3(4,B_), 256>>>(Cg, gam, nullptr);
    }

    dotmul_kernel<<<B_, 256>>>(Cg, gam, dgw);
    copy_kernel<<<512, 256>>>(out + 1 + (size_t)B_*NM, gam, B_*NM);
    final_kernel<<<1, 32>>>(out);
}

// round 5
// speedup vs baseline: 2.8996x; 1.3063x over previous
#include <cuda_runtime.h>
#include <cuda_bf16.h>
#include <cooperative_groups.h>
#include <math.h>

namespace cg = cooperative_groups;

#define B_    32
#define N_IMG 196
#define M_TOK 256
#define D_    1024
#define NM    (N_IMG*M_TOK)
#define KPAD  224     // Cs bf16 row stride (padded 196 -> 224, 16B-aligned)

// ---------------- device scratch (allocation-free) ----------------
__device__ __nv_bfloat16 g_xh[B_*N_IMG*D_];
__device__ __nv_bfloat16 g_xl[B_*N_IMG*D_];
__device__ __nv_bfloat16 g_yh[B_*M_TOK*D_];
__device__ __nv_bfloat16 g_yl[B_*M_TOK*D_];
__device__ float g_Cxy[B_*NM];
__device__ float g_Cs [B_*N_IMG*N_IMG];
__device__ float g_Ct [B_*M_TOK*M_TOK];
__device__ __nv_bfloat16 g_Csh[B_*N_IMG*KPAD];
__device__ __nv_bfloat16 g_Csl[B_*N_IMG*KPAD];
__device__ __nv_bfloat16 g_Cth[B_*M_TOK*M_TOK];
__device__ __nv_bfloat16 g_Ctl[B_*M_TOK*M_TOK];
__device__ __nv_bfloat16 g_gamh[B_*NM];
__device__ __nv_bfloat16 g_gaml[B_*NM];
__device__ __nv_bfloat16 g_tmph[B_*NM];
__device__ __nv_bfloat16 g_tmpl[B_*NM];
__device__ float g_Cg[B_*NM];
__device__ float g_cstrow[B_*N_IMG];
__device__ float g_cstcol[B_*M_TOK];
__device__ unsigned g_minmax[6];
__device__ float g_dotwd[B_];
__device__ float g_dotgw[B_];

// order-preserving float<->uint encoding
__device__ __forceinline__ unsigned enc_mono(float f){
    unsigned u = __float_as_uint(f);
    return (u & 0x80000000u) ? ~u : (u | 0x80000000u);
}
__device__ __forceinline__ float dec_mono(unsigned e){
    unsigned u = (e & 0x80000000u) ? (e ^ 0x80000000u) : ~e;
    return __uint_as_float(u);
}

__device__ __forceinline__ uint32_t smem_u32(const void* p){
    uint32_t a;
    asm("{ .reg .u64 t; cvta.to.shared.u64 t, %1; cvt.u32.u64 %0, t; }" : "=r"(a) : "l"(p));
    return a;
}
__device__ __forceinline__ void ldm_x4(unsigned* r, uint32_t addr){
    asm volatile("ldmatrix.sync.aligned.m8n8.x4.shared.b16 {%0,%1,%2,%3}, [%4];"
        : "=r"(r[0]), "=r"(r[1]), "=r"(r[2]), "=r"(r[3]) : "r"(addr));
}
__device__ __forceinline__ void ldm_x4_t(unsigned* r, uint32_t addr){
    asm volatile("ldmatrix.sync.aligned.m8n8.x4.trans.shared.b16 {%0,%1,%2,%3}, [%4];"
        : "=r"(r[0]), "=r"(r[1]), "=r"(r[2]), "=r"(r[3]) : "r"(addr));
}
__device__ __forceinline__ void mma_bf16(float* d, const unsigned* a, unsigned b0, unsigned b1){
    asm volatile("mma.sync.aligned.m16n8k16.row.col.f32.bf16.bf16.f32 "
        "{%0,%1,%2,%3}, {%4,%5,%6,%7}, {%8,%9}, {%0,%1,%2,%3};"
        : "+f"(d[0]), "+f"(d[1]), "+f"(d[2]), "+f"(d[3])
        : "r"(a[0]), "r"(a[1]), "r"(a[2]), "r"(a[3]), "r"(b0), "r"(b1));
}
__device__ __forceinline__ void split_bf16(float v, __nv_bfloat16& h, __nv_bfloat16& l){
    h = __float2bfloat16(v);
    l = __float2bfloat16(v - __bfloat162float(h));
}

// ---------------- init ----------------
__global__ void init_kernel(){
    int t = threadIdx.x;
    if (t < 3){ g_minmax[2*t] = 0xFFFFFFFFu; g_minmax[2*t+1] = 0u; }
    if (t < B_) g_dotgw[t] = 0.f;
}

// ---------------- normalize: L2 over D, emit bf16 hi/lo split ----------------
__global__ void normalize_kernel(const float* __restrict__ x,
                                 const float* __restrict__ mask,
                                 __nv_bfloat16* __restrict__ oh,
                                 __nv_bfloat16* __restrict__ ol, int npos)
{
    const int bp  = blockIdx.x;
    const int b   = bp / npos;
    const int pos = bp - b*npos;
    const float* v = x + (size_t)bp * D_;
    const float mk = mask ? mask[(size_t)b*npos + pos] : 1.0f;

    float ss = 0.f;
    for (int d = threadIdx.x; d < D_; d += blockDim.x){
        float t = v[d] * mk;
        ss += t*t;
    }
    #pragma unroll
    for (int o = 16; o; o >>= 1) ss += __shfl_xor_sync(0xffffffffu, ss, o);
    __shared__ float sred[8];
    if ((threadIdx.x & 31) == 0) sred[threadIdx.x >> 5] = ss;
    __syncthreads();
    __shared__ float s_inv;
    if (threadIdx.x == 0){
        float t = 0.f;
        for (int w = 0; w < 8; ++w) t += sred[w];
        s_inv = 1.0f / (sqrtf(t) + 1e-12f);
    }
    __syncthreads();
    const float scale = s_inv * mk;
    const size_t base = (size_t)bp * D_;
    for (int d = threadIdx.x; d < D_; d += blockDim.x){
        float t = v[d] * scale;
        __nv_bfloat16 hi, lo; split_bf16(t, hi, lo);
        oh[base + d] = hi;
        ol[base + d] = lo;
    }
}

// ---------------- cosine GEMM via mma.sync bf16 hi/lo split ----------------
#define LDT 40

__global__ void __launch_bounds__(256,1)
cosmma_kernel(const __nv_bfloat16* __restrict__ Ah, const __nv_bfloat16* __restrict__ Al,
              const __nv_bfloat16* __restrict__ Bh, const __nv_bfloat16* __restrict__ Bl,
              float* __restrict__ Cout, int Mz, int Nz, int mmIdx)
{
    __shared__ __align__(16) __nv_bfloat16 sAh[64][LDT];
    __shared__ __align__(16) __nv_bfloat16 sAl[64][LDT];
    __shared__ __align__(16) __nv_bfloat16 sBh[128][LDT];
    __shared__ __align__(16) __nv_bfloat16 sBl[128][LDT];

    const int tid  = threadIdx.x;
    const int lane = tid & 31;
    const int wid  = tid >> 5;
    const int wm   = wid >> 2;
    const int wn   = wid & 3;
    const int b    = blockIdx.z;
    const int m0   = blockIdx.y * 64;
    const int j0   = blockIdx.x * 128;

    const size_t abase = (size_t)b * Mz * D_;
    const size_t bbase = (size_t)b * Nz * D_;

    const int a_row = tid >> 2, a_quad = tid & 3;
    const bool avalid = (m0 + a_row) < Mz;
    const uint4 zero4 = make_uint4(0,0,0,0);

    const uint32_t baAh = smem_u32(&sAh[0][0]);
    const uint32_t baAl = smem_u32(&sAl[0][0]);
    const uint32_t baBh = smem_u32(&sBh[0][0]);
    const uint32_t baBl = smem_u32(&sBl[0][0]);
    const int arow_l = lane & 15, ahalf = lane >> 4;
    const int bg = lane >> 3;
    const int b_noff = ((bg >> 1) << 3) + (lane & 7);
    const int b_koff = (bg & 1) << 3;

    float acc[2][4][4];
    #pragma unroll
    for (int mt = 0; mt < 2; ++mt)
        #pragma unroll
        for (int nt = 0; nt < 4; ++nt)
            #pragma unroll
            for (int q = 0; q < 4; ++q) acc[mt][nt][q] = 0.f;

    for (int kc = 0; kc < 32; ++kc){
        {
            const size_t go = abase + (size_t)(m0 + a_row) * D_ + kc*32 + a_quad*8;
            uint4 vh = zero4, vl = zero4;
            if (avalid){
                vh = *reinterpret_cast<const uint4*>(Ah + go);
                vl = *reinterpret_cast<const uint4*>(Al + go);
            }
            *reinterpret_cast<uint4*>(&sAh[a_row][a_quad*8]) = vh;
            *reinterpret_cast<uint4*>(&sAl[a_row][a_quad*8]) = vl;
        }
        #pragma unroll
        for (int p = 0; p < 2; ++p){
            int idx = tid + p*256;
            int row = idx >> 2, quad = idx & 3;
            const bool bvalid = (j0 + row) < Nz;
            const size_t go = bbase + (size_t)(j0 + row) * D_ + kc*32 + quad*8;
            uint4 vh = zero4, vl = zero4;
            if (bvalid){
                vh = *reinterpret_cast<const uint4*>(Bh + go);
                vl = *reinterpret_cast<const uint4*>(Bl + go);
            }
            *reinterpret_cast<uint4*>(&sBh[row][quad*8]) = vh;
            *reinterpret_cast<uint4*>(&sBl[row][quad*8]) = vl;
        }
        __syncthreads();

        #pragma unroll
        for (int k16 = 0; k16 < 2; ++k16){
            unsigned ah[2][4], al[2][4], bh[2][4], bl[2][4];
            #pragma unroll
            for (int mt = 0; mt < 2; ++mt){
                uint32_t off = (uint32_t)(((wm*32 + mt*16 + arow_l)*LDT + k16*16 + ahalf*8) * 2);
                ldm_x4(ah[mt], baAh + off);
                ldm_x4(al[mt], baAl + off);
            }
            #pragma unroll
            for (int nt2 = 0; nt2 < 2; ++nt2){
                uint32_t off = (uint32_t)(((wn*32 + nt2*16 + b_noff)*LDT + k16*16 + b_koff) * 2);
                ldm_x4(bh[nt2], baBh + off);
                ldm_x4(bl[nt2], baBl + off);
            }
            #pragma unroll
            for (int mt = 0; mt < 2; ++mt)
                #pragma unroll
                for (int nt = 0; nt < 4; ++nt){
                    const int p2 = nt >> 1, s2 = (nt & 1) * 2;
                    mma_bf16(acc[mt][nt], ah[mt], bh[p2][s2], bh[p2][s2+1]);
                    mma_bf16(acc[mt][nt], ah[mt], bl[p2][s2], bl[p2][s2+1]);
                    mma_bf16(acc[mt][nt], al[mt], bh[p2][s2], bh[p2][s2+1]);
                }
        }
        __syncthreads();
    }

    float lmin =  3.402823466e+38f;
    float lmax = -3.402823466e+38f;
    #pragma unroll
    for (int mt = 0; mt < 2; ++mt){
        #pragma unroll
        for (int nt = 0; nt < 4; ++nt){
            const int ibase = m0 + wm*32 + mt*16 + (lane >> 2);
            const int jbase = j0 + wn*32 + nt*8 + (lane & 3)*2;
            #pragma unroll
            for (int rr = 0; rr < 2; ++rr){
                int i = ibase + rr*8;
                if (i >= Mz) continue;
                float* crow = Cout + ((size_t)b*Mz + i)*Nz;
                #pragma unroll
                for (int cc = 0; cc < 2; ++cc){
                    int j = jbase + cc;
                    if (j >= Nz) continue;
                    float v = 1.0f - acc[mt][nt][rr*2 + cc];
                    crow[j] = v;
                    lmin = fminf(lmin, v);
                    lmax = fmaxf(lmax, v);
                }
            }
        }
    }
    #pragma unroll
    for (int o = 16; o; o >>= 1){
        lmin = fminf(lmin, __shfl_xor_sync(0xffffffffu, lmin, o));
        lmax = fmaxf(lmax, __shfl_xor_sync(0xffffffffu, lmax, o));
    }
    if (lane == 0){
        atomicMin(&g_minmax[2*mmIdx],   enc_mono(lmin));
        atomicMax(&g_minmax[2*mmIdx+1], enc_mono(lmax));
    }
}

// ---------------- GW GEMM 1: tmp = Cs @ gamma (bf16-split, B via ldmatrix.trans) ----------------
// A: Csh/Csl [196][KPAD] row-major (K=196, zero-padded). B: gamma bf16 [k][n=256].
// Out: tmph/tmpl [196][256] bf16 split. Grid (2, 4, B_), 256 thr.
#define LDB1 136

__global__ void __launch_bounds__(256,1)
gwmma1_kernel(const __nv_bfloat16* __restrict__ Ah, const __nv_bfloat16* __restrict__ Al,
              const __nv_bfloat16* __restrict__ Bh, const __nv_bfloat16* __restrict__ Bl,
              __nv_bfloat16* __restrict__ Oh, __nv_bfloat16* __restrict__ Ol)
{
    __shared__ __align__(16) __nv_bfloat16 sAh[64][LDT];
    __shared__ __align__(16) __nv_bfloat16 sAl[64][LDT];
    __shared__ __align__(16) __nv_bfloat16 sBh[32][LDB1];
    __shared__ __align__(16) __nv_bfloat16 sBl[32][LDB1];

    const int tid  = threadIdx.x;
    const int lane = tid & 31;
    const int wid  = tid >> 5;
    const int wm   = wid >> 2;
    const int wn   = wid & 3;
    const int b    = blockIdx.z;
    const int m0   = blockIdx.y * 64;
    const int j0   = blockIdx.x * 128;

    const int a_row = tid >> 2, a_quad = tid & 3;
    const bool avalid = (m0 + a_row) < N_IMG;
    const uint4 zero4 = make_uint4(0,0,0,0);

    const uint32_t baAh = smem_u32(&sAh[0][0]);
    const uint32_t baAl = smem_u32(&sAl[0][0]);
    const uint32_t baBh = smem_u32(&sBh[0][0]);
    const uint32_t baBl = smem_u32(&sBl[0][0]);
    const int arow_l = lane & 15, ahalf = lane >> 4;
    const int ktr = ((lane >> 3) & 1)*8 + (lane & 7);   // trans ldmatrix k offset
    const int ntr = (lane >> 4)*8;                       // trans ldmatrix n offset

    float acc[2][4][4];
    #pragma unroll
    for (int mt = 0; mt < 2; ++mt)
        #pragma unroll
        for (int nt = 0; nt < 4; ++nt)
            #pragma unroll
            for (int q = 0; q < 4; ++q) acc[mt][nt][q] = 0.f;

    for (int kc = 0; kc < 7; ++kc){
        const int kbase = kc*32;
        {
            const size_t go = ((size_t)b*N_IMG + (m0 + a_row))*KPAD + kbase + a_quad*8;
            uint4 vh = zero4, vl = zero4;
            if (avalid){
                vh = *reinterpret_cast<const uint4*>(Ah + go);
                vl = *reinterpret_cast<const uint4*>(Al + go);
            }
            *reinterpret_cast<uint4*>(&sAh[a_row][a_quad*8]) = vh;
            *reinterpret_cast<uint4*>(&sAl[a_row][a_quad*8]) = vl;
        }
        #pragma unroll
        for (int p = 0; p < 2; ++p){
            int idx = tid + p*256;
            int kk = idx >> 4, nn = (idx & 15)*8;
            uint4 vh = zero4, vl = zero4;
            if (kbase + kk < N_IMG){
                const size_t go = ((size_t)b*N_IMG + kbase + kk)*M_TOK + j0 + nn;
                vh = *reinterpret_cast<const uint4*>(Bh + go);
                vl = *reinterpret_cast<const uint4*>(Bl + go);
            }
            *reinterpret_cast<uint4*>(&sBh[kk][nn]) = vh;
            *reinterpret_cast<uint4*>(&sBl[kk][nn]) = vl;
        }
        __syncthreads();

        #pragma unroll
        for (int k16 = 0; k16 < 2; ++k16){
            unsigned ah[2][4], al[2][4], bh[2][4], bl[2][4];
            #pragma unroll
            for (int mt = 0; mt < 2; ++mt){
                uint32_t off = (uint32_t)(((wm*32 + mt*16 + arow_l)*LDT + k16*16 + ahalf*8) * 2);
                ldm_x4(ah[mt], baAh + off);
                ldm_x4(al[mt], baAl + off);
            }
            #pragma unroll
            for (int nt2 = 0; nt2 < 2; ++nt2){
                uint32_t off = (uint32_t)(((k16*16 + ktr)*LDB1 + wn*32 + nt2*16 + ntr) * 2);
                ldm_x4_t(bh[nt2], baBh + off);
                ldm_x4_t(bl[nt2], baBl + off);
            }
            #pragma unroll
            for (int mt = 0; mt < 2; ++mt)
                #pragma unroll
                for (int nt = 0; nt < 4; ++nt){
                    const int p2 = nt >> 1, s2 = (nt & 1) * 2;
                    mma_bf16(acc[mt][nt], ah[mt], bh[p2][s2], bh[p2][s2+1]);
                    mma_bf16(acc[mt][nt], ah[mt], bl[p2][s2], bl[p2][s2+1]);
                    mma_bf16(acc[mt][nt], al[mt], bh[p2][s2], bh[p2][s2+1]);
                }
        }
        __syncthreads();
    }

    #pragma unroll
    for (int mt = 0; mt < 2; ++mt){
        #pragma unroll
        for (int nt = 0; nt < 4; ++nt){
            const int ibase = m0 + wm*32 + mt*16 + (lane >> 2);
            const int jbase = j0 + wn*32 + nt*8 + (lane & 3)*2;
            #pragma unroll
            for (int rr = 0; rr < 2; ++rr){
                int i = ibase + rr*8;
                if (i >= N_IMG) continue;
                const size_t ro = ((size_t)b*N_IMG + i)*M_TOK;
                #pragma unroll
                for (int cc = 0; cc < 2; ++cc){
                    int j = jbase + cc;
                    __nv_bfloat16 h, l;
                    split_bf16(acc[mt][nt][rr*2 + cc], h, l);
                    Oh[ro + j] = h;
                    Ol[ro + j] = l;
                }
            }
        }
    }
}

// ---------------- GW GEMM 2: Cg = crow + ccol - 2*(tmp @ Ct^T), optional dot ----------------
// A: tmph/tmpl [196][256]; B: Cth/Ctl [256][256] rows over n (NT). Grid (2,4,B_).
__global__ void __launch_bounds__(256,1)
gwmma2_kernel(const __nv_bfloat16* __restrict__ Ah, const __nv_bfloat16* __restrict__ Al,
              const __nv_bfloat16* __restrict__ Bh, const __nv_bfloat16* __restrict__ Bl,
              float* __restrict__ Cout,
              const float* __restrict__ rowadd, const float* __restrict__ coladd,
              const float* __restrict__ gamF, float* __restrict__ dotOut)
{
    __shared__ __align__(16) __nv_bfloat16 sAh[64][LDT];
    __shared__ __align__(16) __nv_bfloat16 sAl[64][LDT];
    __shared__ __align__(16) __nv_bfloat16 sBh[128][LDT];
    __shared__ __align__(16) __nv_bfloat16 sBl[128][LDT];

    const int tid  = threadIdx.x;
    const int lane = tid & 31;
    const int wid  = tid >> 5;
    const int wm   = wid >> 2;
    const int wn   = wid & 3;
    const int b    = blockIdx.z;
    const int m0   = blockIdx.y * 64;
    const int j0   = blockIdx.x * 128;

    const int a_row = tid >> 2, a_quad = tid & 3;
    const bool avalid = (m0 + a_row) < N_IMG;
    const uint4 zero4 = make_uint4(0,0,0,0);

    const uint32_t baAh = smem_u32(&sAh[0][0]);
    const uint32_t baAl = smem_u32(&sAl[0][0]);
    const uint32_t baBh = smem_u32(&sBh[0][0]);
    const uint32_t baBl = smem_u32(&sBl[0][0]);
    const int arow_l = lane & 15, ahalf = lane >> 4;
    const int bg = lane >> 3;
    const int b_noff = ((bg >> 1) << 3) + (lane & 7);
    const int b_koff = (bg & 1) << 3;

    float acc[2][4][4];
    #pragma unroll
    for (int mt = 0; mt < 2; ++mt)
        #pragma unroll
        for (int nt = 0; nt < 4; ++nt)
            #pragma unroll
            for (int q = 0; q < 4; ++q) acc[mt][nt][q] = 0.f;

    for (int kc = 0; kc < 8; ++kc){
        {
            const size_t go = ((size_t)b*N_IMG + (m0 + a_row))*M_TOK + kc*32 + a_quad*8;
            uint4 vh = zero4, vl = zero4;
            if (avalid){
                vh = *reinterpret_cast<const uint4*>(Ah + go);
                vl = *reinterpret_cast<const uint4*>(Al + go);
            }
            *reinterpret_cast<uint4*>(&sAh[a_row][a_quad*8]) = vh;
            *reinterpret_cast<uint4*>(&sAl[a_row][a_quad*8]) = vl;
        }
        #pragma unroll
        for (int p = 0; p < 2; ++p){
            int idx = tid + p*256;
            int row = idx >> 2, quad = idx & 3;
            const size_t go = ((size_t)b*M_TOK + j0 + row)*M_TOK + kc*32 + quad*8;
            uint4 vh = *reinterpret_cast<const uint4*>(Bh + go);
            uint4 vl = *reinterpret_cast<const uint4*>(Bl + go);
            *reinterpret_cast<uint4*>(&sBh[row][quad*8]) = vh;
            *reinterpret_cast<uint4*>(&sBl[row][quad*8]) = vl;
        }
        __syncthreads();

        #pragma unroll
        for (int k16 = 0; k16 < 2; ++k16){
            unsigned ah[2][4], al[2][4], bh[2][4], bl[2][4];
            #pragma unroll
            for (int mt = 0; mt < 2; ++mt){
                uint32_t off = (uint32_t)(((wm*32 + mt*16 + arow_l)*LDT + k16*16 + ahalf*8) * 2);
                ldm_x4(ah[mt], baAh + off);
                ldm_x4(al[mt], baAl + off);
            }
            #pragma unroll
            for (int nt2 = 0; nt2 < 2; ++nt2){
                uint32_t off = (uint32_t)(((wn*32 + nt2*16 + b_noff)*LDT + k16*16 + b_koff) * 2);
                ldm_x4(bh[nt2], baBh + off);
                ldm_x4(bl[nt2], baBl + off);
            }
            #pragma unroll
            for (int mt = 0; mt < 2; ++mt)
                #pragma unroll
                for (int nt = 0; nt < 4; ++nt){
                    const int p2 = nt >> 1, s2 = (nt & 1) * 2;
                    mma_bf16(acc[mt][nt], ah[mt], bh[p2][s2], bh[p2][s2+1]);
                    mma_bf16(acc[mt][nt], ah[mt], bl[p2][s2], bl[p2][s2+1]);
                    mma_bf16(acc[mt][nt], al[mt], bh[p2][s2], bh[p2][s2+1]);
                }
        }
        __syncthreads();
    }

    float dot = 0.f;
    #pragma unroll
    for (int mt = 0; mt < 2; ++mt){
        #pragma unroll
        for (int nt = 0; nt < 4; ++nt){
            const int ibase = m0 + wm*32 + mt*16 + (lane >> 2);
            const int jbase = j0 + wn*32 + nt*8 + (lane & 3)*2;
            #pragma unroll
            for (int rr = 0; rr < 2; ++rr){
                int i = ibase + rr*8;
                if (i >= N_IMG) continue;
                const size_t ro = ((size_t)b*N_IMG + i)*M_TOK;
                const float ra = rowadd[b*N_IMG + i];
                #pragma unroll
                for (int cc = 0; cc < 2; ++cc){
                    int j = jbase + cc;
                    float r = ra + coladd[b*M_TOK + j] - 2.0f*acc[mt][nt][rr*2 + cc];
                    Cout[ro + j] = r;
                    if (gamF) dot += r * gamF[ro + j];
                }
            }
        }
    }
    if (gamF){
        #pragma unroll
        for (int o = 16; o; o >>= 1) dot += __shfl_xor_sync(0xffffffffu, dot, o);
        if (lane == 0) atomicAdd(&dotOut[b], dot);
    }
}

// ---------------- threshold ReLU ----------------
__global__ void thresh_kernel(float* __restrict__ Carr, const int* __restrict__ maskArr,
                              int total, int pairIdx)
{
    const float mn = dec_mono(g_minmax[2*pairIdx]);
    const float mx = dec_mono(g_minmax[2*pairIdx+1]);
    const float thr = mn + 0.1f*(mx - mn);
    for (int e = blockIdx.x*blockDim.x + threadIdx.x; e < total; e += gridDim.x*blockDim.x){
        float v = Carr[e] - thr;
        v = v > 0.f ? v : 0.f;
        if (maskArr) v *= (maskArr[e] == 1 ? 1.0f : 1e-5f);
        Carr[e] = v;
    }
}

// ---------------- fp32 -> bf16 hi/lo with column padding ----------------
__global__ void convsplit_kernel(const float* __restrict__ src,
                                 __nv_bfloat16* __restrict__ dh, __nv_bfloat16* __restrict__ dl,
                                 int rows, int cols, int padc)
{
    int total = rows * padc;
    for (int e = blockIdx.x*blockDim.x + threadIdx.x; e < total; e += gridDim.x*blockDim.x){
        int r = e / padc, c = e - r*padc;
        float v = (c < cols) ? src[(size_t)r*cols + c] : 0.f;
        __nv_bfloat16 h, l; split_bf16(v, h, l);
        dh[e] = h; dl[e] = l;
    }
}

__global__ void rowmeansq_kernel(const float* __restrict__ A, float* __restrict__ outp, int rowlen)
{
    const float* r = A + (size_t)blockIdx.x * rowlen;
    float ss = 0.f;
    for (int k = threadIdx.x; k < rowlen; k += blockDim.x){
        float t = r[k]; ss += t*t;
    }
    #pragma unroll
    for (int o = 16; o; o >>= 1) ss += __shfl_xor_sync(0xffffffffu, ss, o);
    __shared__ float sred[8];
    if ((threadIdx.x & 31) == 0) sred[threadIdx.x >> 5] = ss;
    __syncthreads();
    if (threadIdx.x == 0){
        float t = 0.f;
        for (int w = 0; w < 8; ++w) t += sred[w];
        outp[blockIdx.x] = t / (float)rowlen;
    }
}

__global__ void fillsplit_kernel(__nv_bfloat16* __restrict__ dh, __nv_bfloat16* __restrict__ dl,
                                 float val, int total)
{
    __nv_bfloat16 h, l; split_bf16(val, h, l);
    for (int e = blockIdx.x*blockDim.x + threadIdx.x; e < total; e += gridDim.x*blockDim.x){
        dh[e] = h; dl[e] = l;
    }
}

// ---------------- IPOT: 4-CTA cluster per batch, E & T register-resident ----------------
// Outputs: optional fp32 T, optional bf16 hi/lo gamma (both [i][j] layout), optional dot.
__global__ void __cluster_dims__(4,1,1) __launch_bounds__(256,1)
ipot_kernel(const float* __restrict__ Cmat, float* __restrict__ ToutF,
            __nv_bfloat16* __restrict__ Gh, __nv_bfloat16* __restrict__ Gl,
            float* __restrict__ dotOut)
{
    cg::cluster_group cluster = cg::this_cluster();
    const int rank = blockIdx.x;
    const int b    = blockIdx.y;
    const int tid  = threadIdx.x;
    const int jl   = tid & 63;
    const int rq   = tid >> 6;
    const int lane = tid & 31;
    const int wid  = tid >> 5;
    const int jg   = rank*64 + jl;
    const float* C = Cmat + (size_t)b * NM;

    __shared__ float s_sigma[64];
    __shared__ float s_delta[196];
    __shared__ float s_part[8][49];
    __shared__ float s_rowpart[2][196];
    __shared__ float s_col[4][64];
    __shared__ float s_dred[8];
    __shared__ float s_dotpart;

    float E[49], T[49];
    #pragma unroll
    for (int k = 0; k < 49; ++k){
        float c = C[(rq + 4*k)*M_TOK + jg];
        E[k] = expf(-2.0f * c);
        T[k] = 1.0f;
    }
    if (tid < 64) s_sigma[tid] = 1.0f/256.0f;
    __syncthreads();

    for (int it = 0; it < 20; ++it){
        const int buf = it & 1;
        const float sig = s_sigma[jl];
        #pragma unroll
        for (int k = 0; k < 49; ++k){
            float v = E[k]*T[k]*sig;
            v += __shfl_xor_sync(0xffffffffu, v, 16);
            v += __shfl_xor_sync(0xffffffffu, v, 8);
            v += __shfl_xor_sync(0xffffffffu, v, 4);
            v += __shfl_xor_sync(0xffffffffu, v, 2);
            v += __shfl_xor_sync(0xffffffffu, v, 1);
            if (lane == 0) s_part[wid][k] = v;
        }
        __syncthreads();
        if (tid < 196){
            int r2 = tid & 3, k2 = tid >> 2;
            s_rowpart[buf][tid] = s_part[r2*2][k2] + s_part[r2*2+1][k2];
        }
        cluster.sync();
        if (tid < 196){
            float s = 0.f;
            #pragma unroll
            for (int r = 0; r < 4; ++r)
                s += *(cluster.map_shared_rank(&s_rowpart[buf][0], r) + tid);
            s_delta[tid] = 1.0f / (196.0f * s);
        }
        __syncthreads();
        float cs = 0.f;
        #pragma unroll
        for (int k = 0; k < 49; ++k)
            cs += E[k]*T[k]*s_delta[rq + 4*k];
        s_col[rq][jl] = cs;
        __syncthreads();
        if (tid < 64){
            float c = s_col[0][tid] + s_col[1][tid] + s_col[2][tid] + s_col[3][tid];
            s_sigma[tid] = 1.0f / (256.0f * c);
        }
        __syncthreads();
        const float sg = s_sigma[jl];
        #pragma unroll
        for (int k = 0; k < 49; ++k)
            T[k] = s_delta[rq + 4*k] * E[k] * T[k] * sg;
    }

    const size_t base = (size_t)b * NM;
    if (ToutF){
        #pragma unroll
        for (int k = 0; k < 49; ++k)
            ToutF[base + (size_t)(rq + 4*k)*M_TOK + jg] = T[k];
    }
    if (Gh){
        #pragma unroll
        for (int k = 0; k < 49; ++k){
            __nv_bfloat16 h, l; split_bf16(T[k], h, l);
            const size_t o = base + (size_t)(rq + 4*k)*M_TOK + jg;
            Gh[o] = h; Gl[o] = l;
        }
    }

    if (dotOut){
        float dot = 0.f;
        #pragma unroll
        for (int k = 0; k < 49; ++k)
            dot += C[(rq + 4*k)*M_TOK + jg] * T[k];
        #pragma unroll
        for (int o = 16; o; o >>= 1) dot += __shfl_xor_sync(0xffffffffu, dot, o);
        if (lane == 0) s_dred[wid] = dot;
        __syncthreads();
        if (tid == 0){
            float t = 0.f;
            for (int w = 0; w < 8; ++w) t += s_dred[w];
            s_dotpart = t;
        }
        cluster.sync();
        if (rank == 0 && tid == 0){
            float t = 0.f;
            #pragma unroll
            for (int r = 0; r < 4; ++r)
                t += *cluster.map_shared_rank(&s_dotpart, r);
            dotOut[b] = t;
        }
    }
    cluster.sync();
}

__global__ void final_kernel(float* __restrict__ outp){
    int t = threadIdx.x;
    float wd = g_dotwd[t];
    float gw = g_dotgw[t];
    #pragma unroll
    for (int o = 16; o; o >>= 1){
        wd += __shfl_xor_sync(0xffffffffu, wd, o);
        gw += __shfl_xor_sync(0xffffffffu, gw, o);
    }
    if (t == 0)
        outp[0] = 0.1f*(gw * (1.0f/B_)) - 0.1f*(wd * (1.0f/B_));
}

// ---------------- host launcher ----------------
extern "C" void kernel_launch(void* const* d_in, const int* in_sizes, int n_in,
                              void* d_out, int out_size)
{
    const float* img     = (const float*)d_in[0];
    const float* tok     = (const float*)d_in[1];
    const float* tokmask = (const float*)d_in[2];
    const int*   tdm     = (const int*)d_in[3];
    const int*   irm     = (const int*)d_in[4];
    float* out = (float*)d_out;                    // [1 | T_wd | T_gwd]
    float* outTwd  = out + 1;
    float* outTgwd = out + 1 + (size_t)B_*NM;

    __nv_bfloat16 *xh, *xl, *yh, *yl, *csh, *csl, *cth, *ctl, *gh, *gl, *th, *tl;
    float *Cxy, *Cs, *Ct, *Cg, *crow, *ccol, *dwd, *dgw;
    cudaGetSymbolAddress((void**)&xh,  g_xh);
    cudaGetSymbolAddress((void**)&xl,  g_xl);
    cudaGetSymbolAddress((void**)&yh,  g_yh);
    cudaGetSymbolAddress((void**)&yl,  g_yl);
    cudaGetSymbolAddress((void**)&csh, g_Csh);
    cudaGetSymbolAddress((void**)&csl, g_Csl);
    cudaGetSymbolAddress((void**)&cth, g_Cth);
    cudaGetSymbolAddress((void**)&ctl, g_Ctl);
    cudaGetSymbolAddress((void**)&gh,  g_gamh);
    cudaGetSymbolAddress((void**)&gl,  g_gaml);
    cudaGetSymbolAddress((void**)&th,  g_tmph);
    cudaGetSymbolAddress((void**)&tl,  g_tmpl);
    cudaGetSymbolAddress((void**)&Cxy, g_Cxy);
    cudaGetSymbolAddress((void**)&Cs,  g_Cs);
    cudaGetSymbolAddress((void**)&Ct,  g_Ct);
    cudaGetSymbolAddress((void**)&Cg,  g_Cg);
    cudaGetSymbolAddress((void**)&crow, g_cstrow);
    cudaGetSymbolAddress((void**)&ccol, g_cstcol);
    cudaGetSymbolAddress((void**)&dwd, g_dotwd);
    cudaGetSymbolAddress((void**)&dgw, g_dotgw);

    init_kernel<<<1, 64>>>();
    normalize_kernel<<<B_*N_IMG, 256>>>(img, nullptr, xh, xl, N_IMG);
    normalize_kernel<<<B_*M_TOK, 256>>>(tok, tokmask, yh, yl, M_TOK);

    cosmma_kernel<<<dim3(2,4,B_), 256>>>(xh, xl, yh, yl, Cxy, N_IMG, M_TOK, 0);
    cosmma_kernel<<<dim3(2,4,B_), 256>>>(xh, xl, xh, xl, Cs,  N_IMG, N_IMG, 1);
    cosmma_kernel<<<dim3(2,4,B_), 256>>>(yh, yl, yh, yl, Ct,  M_TOK, M_TOK, 2);

    thresh_kernel<<<1024, 256>>>(Cxy, nullptr, B_*NM, 0);
    thresh_kernel<<<1024, 256>>>(Cs,  irm, B_*N_IMG*N_IMG, 1);
    thresh_kernel<<<1024, 256>>>(Ct,  tdm, B_*M_TOK*M_TOK, 2);

    // bf16-split copies of Cs (K-padded) and Ct for the GW tensor-core chain
    convsplit_kernel<<<512, 256>>>(Cs, csh, csl, B_*N_IMG, N_IMG, KPAD);
    convsplit_kernel<<<512, 256>>>(Ct, cth, ctl, B_*M_TOK, M_TOK, M_TOK);

    // Wasserstein IPOT -> T_wd + per-batch dot
    ipot_kernel<<<dim3(4,B_), 256>>>(Cxy, outTwd, nullptr, nullptr, dwd);

    rowmeansq_kernel<<<B_*N_IMG, 256>>>(Cs, crow, N_IMG);
    rowmeansq_kernel<<<B_*M_TOK, 256>>>(Ct, ccol, M_TOK);
    fillsplit_kernel<<<512, 256>>>(gh, gl, 1.0f/(float)NM, B_*NM);

    for (int it = 0; it < 6; ++it){
        gwmma1_kernel<<<dim3(2,4,B_), 256>>>(csh, csl, gh, gl, th, tl);
        const bool last = (it == 5);
        gwmma2_kernel<<<dim3(2,4,B_), 256>>>(th, tl, cth, ctl, Cg, crow, ccol,
                                             last ? outTgwd : nullptr, dgw);
        if (it < 5)
            ipot_kernel<<<dim3(4,B_), 256>>>(Cg, (it == 4) ? outTgwd : nullptr, gh, gl, nullptr);
    }

    final_kernel<<<1, 32>>>(out);
}

// round 6
// speedup vs baseline: 3.0858x; 1.0642x over previous
#include <cuda_runtime.h>
#include <cuda_bf16.h>
#include <cooperative_groups.h>
#include <math.h>

namespace cg = cooperative_groups;

#define B_    32
#define N_IMG 196
#define M_TOK 256
#define D_    1024
#define NM    (N_IMG*M_TOK)
#define KPAD  224

// ---------------- device scratch (allocation-free) ----------------
__device__ __nv_bfloat16 g_xh[B_*N_IMG*D_];
__device__ __nv_bfloat16 g_xl[B_*N_IMG*D_];
__device__ __nv_bfloat16 g_yh[B_*M_TOK*D_];
__device__ __nv_bfloat16 g_yl[B_*M_TOK*D_];
__device__ float g_Cxy[B_*NM];
__device__ float g_Cs [B_*N_IMG*N_IMG];
__device__ float g_Ct [B_*M_TOK*M_TOK];
__device__ __nv_bfloat16 g_Csh[B_*N_IMG*KPAD];
__device__ __nv_bfloat16 g_Csl[B_*N_IMG*KPAD];
__device__ __nv_bfloat16 g_Cth[B_*M_TOK*M_TOK];
__device__ __nv_bfloat16 g_Ctl[B_*M_TOK*M_TOK];
__device__ __nv_bfloat16 g_gamh[B_*NM];
__device__ __nv_bfloat16 g_gaml[B_*NM];
__device__ __nv_bfloat16 g_tmph[B_*NM];
__device__ __nv_bfloat16 g_tmpl[B_*NM];
__device__ float g_Cg[B_*NM];
__device__ float g_cstrow[B_*N_IMG];
__device__ float g_cstcol[B_*M_TOK];
__device__ unsigned g_minmax[6];
__device__ float g_dotwd[B_];
__device__ float g_dotgw[B_];

__device__ __forceinline__ unsigned enc_mono(float f){
    unsigned u = __float_as_uint(f);
    return (u & 0x80000000u) ? ~u : (u | 0x80000000u);
}
__device__ __forceinline__ float dec_mono(unsigned e){
    unsigned u = (e & 0x80000000u) ? (e ^ 0x80000000u) : ~e;
    return __uint_as_float(u);
}
__device__ __forceinline__ uint32_t smem_u32(const void* p){
    uint32_t a;
    asm("{ .reg .u64 t; cvta.to.shared.u64 t, %1; cvt.u32.u64 %0, t; }" : "=r"(a) : "l"(p));
    return a;
}
__device__ __forceinline__ void ldm_x4(unsigned* r, uint32_t addr){
    asm volatile("ldmatrix.sync.aligned.m8n8.x4.shared.b16 {%0,%1,%2,%3}, [%4];"
        : "=r"(r[0]), "=r"(r[1]), "=r"(r[2]), "=r"(r[3]) : "r"(addr));
}
__device__ __forceinline__ void ldm_x4_t(unsigned* r, uint32_t addr){
    asm volatile("ldmatrix.sync.aligned.m8n8.x4.trans.shared.b16 {%0,%1,%2,%3}, [%4];"
        : "=r"(r[0]), "=r"(r[1]), "=r"(r[2]), "=r"(r[3]) : "r"(addr));
}
__device__ __forceinline__ void mma_bf16(float* d, const unsigned* a, unsigned b0, unsigned b1){
    asm volatile("mma.sync.aligned.m16n8k16.row.col.f32.bf16.bf16.f32 "
        "{%0,%1,%2,%3}, {%4,%5,%6,%7}, {%8,%9}, {%0,%1,%2,%3};"
        : "+f"(d[0]), "+f"(d[1]), "+f"(d[2]), "+f"(d[3])
        : "r"(a[0]), "r"(a[1]), "r"(a[2]), "r"(a[3]), "r"(b0), "r"(b1));
}
__device__ __forceinline__ void split_bf16(float v, __nv_bfloat16& h, __nv_bfloat16& l){
    h = __float2bfloat16(v);
    l = __float2bfloat16(v - __bfloat162float(h));
}
// cp.async 16B with zero-fill when invalid (src clamped to a valid address)
__device__ __forceinline__ void cp16(uint32_t d, const void* s, bool v){
    int sz = v ? 16 : 0;
    asm volatile("cp.async.ca.shared.global [%0], [%1], 16, %2;" :: "r"(d), "l"(s), "r"(sz));
}
#define CP_COMMIT() asm volatile("cp.async.commit_group;" ::: "memory")
#define CP_WAIT1()  asm volatile("cp.async.wait_group 1;" ::: "memory")
#define CP_WAIT0()  asm volatile("cp.async.wait_group 0;" ::: "memory")

// ---------------- init ----------------
__global__ void init_kernel(){
    int t = threadIdx.x;
    if (t < 3){ g_minmax[2*t] = 0xFFFFFFFFu; g_minmax[2*t+1] = 0u; }
    if (t < B_) g_dotgw[t] = 0.f;
}

// ---------------- normalize: L2 over D, emit bf16 hi/lo split ----------------
__global__ void normalize_kernel(const float* __restrict__ x,
                                 const float* __restrict__ mask,
                                 __nv_bfloat16* __restrict__ oh,
                                 __nv_bfloat16* __restrict__ ol, int npos)
{
    const int bp  = blockIdx.x;
    const int b   = bp / npos;
    const int pos = bp - b*npos;
    const float* v = x + (size_t)bp * D_;
    const float mk = mask ? mask[(size_t)b*npos + pos] : 1.0f;

    float ss = 0.f;
    for (int d = threadIdx.x; d < D_; d += blockDim.x){
        float t = v[d] * mk;
        ss += t*t;
    }
    #pragma unroll
    for (int o = 16; o; o >>= 1) ss += __shfl_xor_sync(0xffffffffu, ss, o);
    __shared__ float sred[8];
    if ((threadIdx.x & 31) == 0) sred[threadIdx.x >> 5] = ss;
    __syncthreads();
    __shared__ float s_inv;
    if (threadIdx.x == 0){
        float t = 0.f;
        for (int w = 0; w < 8; ++w) t += sred[w];
        s_inv = 1.0f / (sqrtf(t) + 1e-12f);
    }
    __syncthreads();
    const float scale = s_inv * mk;
    const size_t base = (size_t)bp * D_;
    for (int d = threadIdx.x; d < D_; d += blockDim.x){
        float t = v[d] * scale;
        __nv_bfloat16 hi, lo; split_bf16(t, hi, lo);
        oh[base + d] = hi;
        ol[base + d] = lo;
    }
}

// ============ cosine GEMM: cp.async double-buffered, bf16 hi/lo split ============
// dyn smem layout (bytes): AH buf*5120 [0,10240) | AL [10240,20480)
//                          BH 20480+buf*10240 [20480,40960) | BL [40960,61440)
#define LDT 40
#define COS_DSM 61440

__global__ void __launch_bounds__(256,1)
cosmma_kernel(const __nv_bfloat16* __restrict__ Ah, const __nv_bfloat16* __restrict__ Al,
              const __nv_bfloat16* __restrict__ Bh, const __nv_bfloat16* __restrict__ Bl,
              float* __restrict__ Cout, int Mz, int Nz, int mmIdx)
{
    extern __shared__ char dyn[];
    const uint32_t sb = smem_u32(dyn);

    const int tid  = threadIdx.x;
    const int lane = tid & 31;
    const int wid  = tid >> 5;
    const int wm   = wid >> 2;
    const int wn   = wid & 3;
    const int b    = blockIdx.z;
    const int m0   = blockIdx.y * 64;
    const int j0   = blockIdx.x * 128;

    const size_t abase = (size_t)b * Mz * D_;
    const size_t bbase = (size_t)b * Nz * D_;

    const int a_row = tid >> 2, a_quad = tid & 3;
    const bool avalid = (m0 + a_row) < Mz;
    const uint32_t aoff = (uint32_t)((a_row*LDT + a_quad*8) * 2);

    const int arow_l = lane & 15, ahalf = lane >> 4;
    const int bg = lane >> 3;
    const int b_noff = ((bg >> 1) << 3) + (lane & 7);
    const int b_koff = (bg & 1) << 3;

    float acc[2][4][4];
    #pragma unroll
    for (int mt = 0; mt < 2; ++mt)
        #pragma unroll
        for (int nt = 0; nt < 4; ++nt)
            #pragma unroll
            for (int q = 0; q < 4; ++q) acc[mt][nt][q] = 0.f;

    // tile loader via cp.async
    auto issue_tile = [&](int kc, int buf){
        const uint32_t ah = sb + buf*5120u;
        const uint32_t al = sb + 10240u + buf*5120u;
        const uint32_t bh = sb + 20480u + buf*10240u;
        const uint32_t bl = sb + 40960u + buf*10240u;
        {
            const size_t go = abase + (size_t)(m0 + a_row)*D_ + kc*32 + a_quad*8;
            const size_t gs = avalid ? go : abase;
            cp16(ah + aoff, Ah + gs, avalid);
            cp16(al + aoff, Al + gs, avalid);
        }
        #pragma unroll
        for (int p = 0; p < 2; ++p){
            int idx = tid + p*256;
            int row = idx >> 2, quad = idx & 3;
            const bool bv = (j0 + row) < Nz;
            const size_t go = bbase + (size_t)(j0 + row)*D_ + kc*32 + quad*8;
            const size_t gs = bv ? go : bbase;
            const uint32_t so = (uint32_t)((row*LDT + quad*8) * 2);
            cp16(bh + so, Bh + gs, bv);
            cp16(bl + so, Bl + gs, bv);
        }
        CP_COMMIT();
    };

    issue_tile(0, 0);
    for (int kc = 0; kc < 32; ++kc){
        if (kc < 31){ issue_tile(kc+1, (kc+1)&1); CP_WAIT1(); }
        else        { CP_WAIT0(); }
        __syncthreads();

        const int buf = kc & 1;
        const uint32_t baAh = sb + buf*5120u;
        const uint32_t baAl = sb + 10240u + buf*5120u;
        const uint32_t baBh = sb + 20480u + buf*10240u;
        const uint32_t baBl = sb + 40960u + buf*10240u;

        #pragma unroll
        for (int k16 = 0; k16 < 2; ++k16){
            unsigned ah[2][4], al[2][4], bh[2][4], bl[2][4];
            #pragma unroll
            for (int mt = 0; mt < 2; ++mt){
                uint32_t off = (uint32_t)(((wm*32 + mt*16 + arow_l)*LDT + k16*16 + ahalf*8) * 2);
                ldm_x4(ah[mt], baAh + off);
                ldm_x4(al[mt], baAl + off);
            }
            #pragma unroll
            for (int nt2 = 0; nt2 < 2; ++nt2){
                uint32_t off = (uint32_t)(((wn*32 + nt2*16 + b_noff)*LDT + k16*16 + b_koff) * 2);
                ldm_x4(bh[nt2], baBh + off);
                ldm_x4(bl[nt2], baBl + off);
            }
            #pragma unroll
            for (int mt = 0; mt < 2; ++mt)
                #pragma unroll
                for (int nt = 0; nt < 4; ++nt){
                    const int p2 = nt >> 1, s2 = (nt & 1) * 2;
                    mma_bf16(acc[mt][nt], ah[mt], bh[p2][s2], bh[p2][s2+1]);
                    mma_bf16(acc[mt][nt], ah[mt], bl[p2][s2], bl[p2][s2+1]);
                    mma_bf16(acc[mt][nt], al[mt], bh[p2][s2], bh[p2][s2+1]);
                }
        }
        __syncthreads();
    }

    float lmin =  3.402823466e+38f;
    float lmax = -3.402823466e+38f;
    #pragma unroll
    for (int mt = 0; mt < 2; ++mt){
        #pragma unroll
        for (int nt = 0; nt < 4; ++nt){
            const int ibase = m0 + wm*32 + mt*16 + (lane >> 2);
            const int jbase = j0 + wn*32 + nt*8 + (lane & 3)*2;
            #pragma unroll
            for (int rr = 0; rr < 2; ++rr){
                int i = ibase + rr*8;
                if (i >= Mz) continue;
                float* crow = Cout + ((size_t)b*Mz + i)*Nz;
                #pragma unroll
                for (int cc = 0; cc < 2; ++cc){
                    int j = jbase + cc;
                    if (j >= Nz) continue;
                    float v = 1.0f - acc[mt][nt][rr*2 + cc];
                    crow[j] = v;
                    lmin = fminf(lmin, v);
                    lmax = fmaxf(lmax, v);
                }
            }
        }
    }
    #pragma unroll
    for (int o = 16; o; o >>= 1){
        lmin = fminf(lmin, __shfl_xor_sync(0xffffffffu, lmin, o));
        lmax = fmaxf(lmax, __shfl_xor_sync(0xffffffffu, lmax, o));
    }
    if (lane == 0){
        atomicMin(&g_minmax[2*mmIdx],   enc_mono(lmin));
        atomicMax(&g_minmax[2*mmIdx+1], enc_mono(lmax));
    }
}

// ============ GW GEMM 1: tmp = Cs @ gamma (cp.async pipelined) ============
// dyn layout: AH buf*5120 [0,10240) | AL [10240,20480)
//             BH 20480+buf*8704 [20480,37888) | BL 37888+buf*8704 [37888,55296)
#define LDB1 136
#define GW1_DSM 55296

__global__ void __launch_bounds__(256,1)
gwmma1_kernel(const __nv_bfloat16* __restrict__ Ah, const __nv_bfloat16* __restrict__ Al,
              const __nv_bfloat16* __restrict__ Bh, const __nv_bfloat16* __restrict__ Bl,
              __nv_bfloat16* __restrict__ Oh, __nv_bfloat16* __restrict__ Ol)
{
    extern __shared__ char dyn[];
    const uint32_t sb = smem_u32(dyn);

    const int tid  = threadIdx.x;
    const int lane = tid & 31;
    const int wid  = tid >> 5;
    const int wm   = wid >> 2;
    const int wn   = wid & 3;
    const int b    = blockIdx.z;
    const int m0   = blockIdx.y * 64;
    const int j0   = blockIdx.x * 128;

    const int a_row = tid >> 2, a_quad = tid & 3;
    const bool avalid = (m0 + a_row) < N_IMG;
    const uint32_t aoff = (uint32_t)((a_row*LDT + a_quad*8) * 2);

    const int arow_l = lane & 15, ahalf = lane >> 4;
    const int ktr = ((lane >> 3) & 1)*8 + (lane & 7);
    const int ntr = (lane >> 4)*8;

    float acc[2][4][4];
    #pragma unroll
    for (int mt = 0; mt < 2; ++mt)
        #pragma unroll
        for (int nt = 0; nt < 4; ++nt)
            #pragma unroll
            for (int q = 0; q < 4; ++q) acc[mt][nt][q] = 0.f;

    auto issue_tile = [&](int kc, int buf){
        const uint32_t ah = sb + buf*5120u;
        const uint32_t al = sb + 10240u + buf*5120u;
        const uint32_t bh = sb + 20480u + buf*8704u;
        const uint32_t bl = sb + 37888u + buf*8704u;
        const int kbase = kc*32;
        {
            const size_t go = ((size_t)b*N_IMG + (m0 + a_row))*KPAD + kbase + a_quad*8;
            const size_t gs = avalid ? go : (size_t)b*N_IMG*KPAD;
            cp16(ah + aoff, Ah + gs, avalid);
            cp16(al + aoff, Al + gs, avalid);
        }
        #pragma unroll
        for (int p = 0; p < 2; ++p){
            int idx = tid + p*256;
            int kk = idx >> 4, nn = (idx & 15)*8;
            const bool bv = (kbase + kk) < N_IMG;
            const size_t go = ((size_t)b*N_IMG + kbase + kk)*M_TOK + j0 + nn;
            const size_t gs = bv ? go : (size_t)b*NM;
            const uint32_t so = (uint32_t)((kk*LDB1 + nn) * 2);
            cp16(bh + so, Bh + gs, bv);
            cp16(bl + so, Bl + gs, bv);
        }
        CP_COMMIT();
    };

    issue_tile(0, 0);
    for (int kc = 0; kc < 7; ++kc){
        if (kc < 6){ issue_tile(kc+1, (kc+1)&1); CP_WAIT1(); }
        else       { CP_WAIT0(); }
        __syncthreads();

        const int buf = kc & 1;
        const uint32_t baAh = sb + buf*5120u;
        const uint32_t baAl = sb + 10240u + buf*5120u;
        const uint32_t baBh = sb + 20480u + buf*8704u;
        const uint32_t baBl = sb + 37888u + buf*8704u;

        #pragma unroll
        for (int k16 = 0; k16 < 2; ++k16){
            unsigned ah[2][4], al[2][4], bh[2][4], bl[2][4];
            #pragma unroll
            for (int mt = 0; mt < 2; ++mt){
                uint32_t off = (uint32_t)(((wm*32 + mt*16 + arow_l)*LDT + k16*16 + ahalf*8) * 2);
                ldm_x4(ah[mt], baAh + off);
                ldm_x4(al[mt], baAl + off);
            }
            #pragma unroll
            for (int nt2 = 0; nt2 < 2; ++nt2){
                uint32_t off = (uint32_t)(((k16*16 + ktr)*LDB1 + wn*32 + nt2*16 + ntr) * 2);
                ldm_x4_t(bh[nt2], baBh + off);
                ldm_x4_t(bl[nt2], baBl + off);
            }
            #pragma unroll
            for (int mt = 0; mt < 2; ++mt)
                #pragma unroll
                for (int nt = 0; nt < 4; ++nt){
                    const int p2 = nt >> 1, s2 = (nt & 1) * 2;
                    mma_bf16(acc[mt][nt], ah[mt], bh[p2][s2], bh[p2][s2+1]);
                    mma_bf16(acc[mt][nt], ah[mt], bl[p2][s2], bl[p2][s2+1]);
                    mma_bf16(acc[mt][nt], al[mt], bh[p2][s2], bh[p2][s2+1]);
                }
        }
        __syncthreads();
    }

    #pragma unroll
    for (int mt = 0; mt < 2; ++mt){
        #pragma unroll
        for (int nt = 0; nt < 4; ++nt){
            const int ibase = m0 + wm*32 + mt*16 + (lane >> 2);
            const int jbase = j0 + wn*32 + nt*8 + (lane & 3)*2;
            #pragma unroll
            for (int rr = 0; rr < 2; ++rr){
                int i = ibase + rr*8;
                if (i >= N_IMG) continue;
                const size_t ro = ((size_t)b*N_IMG + i)*M_TOK;
                #pragma unroll
                for (int cc = 0; cc < 2; ++cc){
                    int j = jbase + cc;
                    __nv_bfloat16 h, l;
                    split_bf16(acc[mt][nt][rr*2 + cc], h, l);
                    Oh[ro + j] = h;
                    Ol[ro + j] = l;
                }
            }
        }
    }
}

// ============ GW GEMM 2: Cg = crow+ccol-2*(tmp@Ct^T) (cp.async pipelined) ============
__global__ void __launch_bounds__(256,1)
gwmma2_kernel(const __nv_bfloat16* __restrict__ Ah, const __nv_bfloat16* __restrict__ Al,
              const __nv_bfloat16* __restrict__ Bh, const __nv_bfloat16* __restrict__ Bl,
              float* __restrict__ Cout,
              const float* __restrict__ rowadd, const float* __restrict__ coladd,
              const float* __restrict__ gamF, float* __restrict__ dotOut)
{
    extern __shared__ char dyn[];
    const uint32_t sb = smem_u32(dyn);

    const int tid  = threadIdx.x;
    const int lane = tid & 31;
    const int wid  = tid >> 5;
    const int wm   = wid >> 2;
    const int wn   = wid & 3;
    const int b    = blockIdx.z;
    const int m0   = blockIdx.y * 64;
    const int j0   = blockIdx.x * 128;

    const int a_row = tid >> 2, a_quad = tid & 3;
    const bool avalid = (m0 + a_row) < N_IMG;
    const uint32_t aoff = (uint32_t)((a_row*LDT + a_quad*8) * 2);

    const int arow_l = lane & 15, ahalf = lane >> 4;
    const int bg = lane >> 3;
    const int b_noff = ((bg >> 1) << 3) + (lane & 7);
    const int b_koff = (bg & 1) << 3;

    float acc[2][4][4];
    #pragma unroll
    for (int mt = 0; mt < 2; ++mt)
        #pragma unroll
        for (int nt = 0; nt < 4; ++nt)
            #pragma unroll
            for (int q = 0; q < 4; ++q) acc[mt][nt][q] = 0.f;

    auto issue_tile = [&](int kc, int buf){
        const uint32_t ah = sb + buf*5120u;
        const uint32_t al = sb + 10240u + buf*5120u;
        const uint32_t bh = sb + 20480u + buf*10240u;
        const uint32_t bl = sb + 40960u + buf*10240u;
        {
            const size_t go = ((size_t)b*N_IMG + (m0 + a_row))*M_TOK + kc*32 + a_quad*8;
            const size_t gs = avalid ? go : (size_t)b*NM;
            cp16(ah + aoff, Ah + gs, avalid);
            cp16(al + aoff, Al + gs, avalid);
        }
        #pragma unroll
        for (int p = 0; p < 2; ++p){
            int idx = tid + p*256;
            int row = idx >> 2, quad = idx & 3;
            const size_t go = ((size_t)b*M_TOK + j0 + row)*M_TOK + kc*32 + quad*8;
            const uint32_t so = (uint32_t)((row*LDT + quad*8) * 2);
            cp16(bh + so, Bh + go, true);
            cp16(bl + so, Bl + go, true);
        }
        CP_COMMIT();
    };

    issue_tile(0, 0);
    for (int kc = 0; kc < 8; ++kc){
        if (kc < 7){ issue_tile(kc+1, (kc+1)&1); CP_WAIT1(); }
        else       { CP_WAIT0(); }
        __syncthreads();

        const int buf = kc & 1;
        const uint32_t baAh = sb + buf*5120u;
        const uint32_t baAl = sb + 10240u + buf*5120u;
        const uint32_t baBh = sb + 20480u + buf*10240u;
        const uint32_t baBl = sb + 40960u + buf*10240u;

        #pragma unroll
        for (int k16 = 0; k16 < 2; ++k16){
            unsigned ah[2][4], al[2][4], bh[2][4], bl[2][4];
            #pragma unroll
            for (int mt = 0; mt < 2; ++mt){
                uint32_t off = (uint32_t)(((wm*32 + mt*16 + arow_l)*LDT + k16*16 + ahalf*8) * 2);
                ldm_x4(ah[mt], baAh + off);
                ldm_x4(al[mt], baAl + off);
            }
            #pragma unroll
            for (int nt2 = 0; nt2 < 2; ++nt2){
                uint32_t off = (uint32_t)(((wn*32 + nt2*16 + b_noff)*LDT + k16*16 + b_koff) * 2);
                ldm_x4(bh[nt2], baBh + off);
                ldm_x4(bl[nt2], baBl + off);
            }
            #pragma unroll
            for (int mt = 0; mt < 2; ++mt)
                #pragma unroll
                for (int nt = 0; nt < 4; ++nt){
                    const int p2 = nt >> 1, s2 = (nt & 1) * 2;
                    mma_bf16(acc[mt][nt], ah[mt], bh[p2][s2], bh[p2][s2+1]);
                    mma_bf16(acc[mt][nt], ah[mt], bl[p2][s2], bl[p2][s2+1]);
                    mma_bf16(acc[mt][nt], al[mt], bh[p2][s2], bh[p2][s2+1]);
                }
        }
        __syncthreads();
    }

    float dot = 0.f;
    #pragma unroll
    for (int mt = 0; mt < 2; ++mt){
        #pragma unroll
        for (int nt = 0; nt < 4; ++nt){
            const int ibase = m0 + wm*32 + mt*16 + (lane >> 2);
            const int jbase = j0 + wn*32 + nt*8 + (lane & 3)*2;
            #pragma unroll
            for (int rr = 0; rr < 2; ++rr){
                int i = ibase + rr*8;
                if (i >= N_IMG) continue;
                const size_t ro = ((size_t)b*N_IMG + i)*M_TOK;
                const float ra = rowadd[b*N_IMG + i];
                #pragma unroll
                for (int cc = 0; cc < 2; ++cc){
                    int j = jbase + cc;
                    float r = ra + coladd[b*M_TOK + j] - 2.0f*acc[mt][nt][rr*2 + cc];
                    Cout[ro + j] = r;
                    if (gamF) dot += r * gamF[ro + j];
                }
            }
        }
    }
    if (gamF){
        #pragma unroll
        for (int o = 16; o; o >>= 1) dot += __shfl_xor_sync(0xffffffffu, dot, o);
        if (lane == 0) atomicAdd(&dotOut[b], dot);
    }
}

// ---------------- threshold ReLU (fp32 only, for Cxy) ----------------
__global__ void thresh_kernel(float* __restrict__ Carr, int total, int pairIdx)
{
    const float mn = dec_mono(g_minmax[2*pairIdx]);
    const float mx = dec_mono(g_minmax[2*pairIdx+1]);
    const float thr = mn + 0.1f*(mx - mn);
    for (int e = blockIdx.x*blockDim.x + threadIdx.x; e < total; e += gridDim.x*blockDim.x){
        float v = Carr[e] - thr;
        Carr[e] = v > 0.f ? v : 0.f;
    }
}

// ---------------- fused threshold + mask + fp32 writeback + bf16 split (padded) ----------------
__global__ void threshsplit_kernel(float* __restrict__ Carr, const int* __restrict__ maskArr,
                                   __nv_bfloat16* __restrict__ dh, __nv_bfloat16* __restrict__ dl,
                                   int rows, int cols, int padc, int pairIdx)
{
    const float mn = dec_mono(g_minmax[2*pairIdx]);
    const float mx = dec_mono(g_minmax[2*pairIdx+1]);
    const float thr = mn + 0.1f*(mx - mn);
    const int total = B_ * rows * padc;
    for (int e = blockIdx.x*blockDim.x + threadIdx.x; e < total; e += gridDim.x*blockDim.x){
        int r = e / padc, c = e - r*padc;   // r in [0, B_*rows)
        float v = 0.f;
        if (c < cols){
            size_t si = (size_t)r*cols + c;
            v = Carr[si] - thr;
            v = v > 0.f ? v : 0.f;
            v *= (maskArr[si] == 1 ? 1.0f : 1e-5f);
            Carr[si] = v;
        }
        __nv_bfloat16 h, l; split_bf16(v, h, l);
        dh[e] = h; dl[e] = l;
    }
}

__global__ void rowmeansq_kernel(const float* __restrict__ A, float* __restrict__ outp, int rowlen)
{
    const float* r = A + (size_t)blockIdx.x * rowlen;
    float ss = 0.f;
    for (int k = threadIdx.x; k < rowlen; k += blockDim.x){
        float t = r[k]; ss += t*t;
    }
    #pragma unroll
    for (int o = 16; o; o >>= 1) ss += __shfl_xor_sync(0xffffffffu, ss, o);
    __shared__ float sred[8];
    if ((threadIdx.x & 31) == 0) sred[threadIdx.x >> 5] = ss;
    __syncthreads();
    if (threadIdx.x == 0){
        float t = 0.f;
        for (int w = 0; w < 8; ++w) t += sred[w];
        outp[blockIdx.x] = t / (float)rowlen;
    }
}

__global__ void fillsplit_kernel(__nv_bfloat16* __restrict__ dh, __nv_bfloat16* __restrict__ dl,
                                 float val, int total)
{
    __nv_bfloat16 h, l; split_bf16(val, h, l);
    for (int e = blockIdx.x*blockDim.x + threadIdx.x; e < total; e += gridDim.x*blockDim.x){
        dh[e] = h; dl[e] = l;
    }
}

// ---------------- IPOT: 4-CTA cluster per batch, E & T register-resident ----------------
__global__ void __cluster_dims__(4,1,1) __launch_bounds__(256,1)
ipot_kernel(const float* __restrict__ Cmat, float* __restrict__ ToutF,
            __nv_bfloat16* __restrict__ Gh, __nv_bfloat16* __restrict__ Gl,
            float* __restrict__ dotOut)
{
    cg::cluster_group cluster = cg::this_cluster();
    const int rank = blockIdx.x;
    const int b    = blockIdx.y;
    const int tid  = threadIdx.x;
    const int jl   = tid & 63;
    const int rq   = tid >> 6;
    const int lane = tid & 31;
    const int wid  = tid >> 5;
    const int jg   = rank*64 + jl;
    const float* C = Cmat + (size_t)b * NM;

    __shared__ float s_sigma[64];
    __shared__ float s_delta[196];
    __shared__ float s_part[8][49];
    __shared__ float s_rowpart[2][196];
    __shared__ float s_col[4][64];
    __shared__ float s_dred[8];
    __shared__ float s_dotpart;

    float E[49], T[49];
    #pragma unroll
    for (int k = 0; k < 49; ++k){
        float c = C[(rq + 4*k)*M_TOK + jg];
        E[k] = expf(-2.0f * c);
        T[k] = 1.0f;
    }
    if (tid < 64) s_sigma[tid] = 1.0f/256.0f;
    __syncthreads();

    for (int it = 0; it < 20; ++it){
        const int buf = it & 1;
        const float sig = s_sigma[jl];
        #pragma unroll
        for (int k = 0; k < 49; ++k){
            float v = E[k]*T[k]*sig;
            v += __shfl_xor_sync(0xffffffffu, v, 16);
            v += __shfl_xor_sync(0xffffffffu, v, 8);
            v += __shfl_xor_sync(0xffffffffu, v, 4);
            v += __shfl_xor_sync(0xffffffffu, v, 2);
            v += __shfl_xor_sync(0xffffffffu, v, 1);
            if (lane == 0) s_part[wid][k] = v;
        }
        __syncthreads();
        if (tid < 196){
            int r2 = tid & 3, k2 = tid >> 2;
            s_rowpart[buf][tid] = s_part[r2*2][k2] + s_part[r2*2+1][k2];
        }
        cluster.sync();
        if (tid < 196){
            float s = 0.f;
            #pragma unroll
            for (int r = 0; r < 4; ++r)
                s += *(cluster.map_shared_rank(&s_rowpart[buf][0], r) + tid);
            s_delta[tid] = 1.0f / (196.0f * s);
        }
        __syncthreads();
        float cs = 0.f;
        #pragma unroll
        for (int k = 0; k < 49; ++k)
            cs += E[k]*T[k]*s_delta[rq + 4*k];
        s_col[rq][jl] = cs;
        __syncthreads();
        if (tid < 64){
            float c = s_col[0][tid] + s_col[1][tid] + s_col[2][tid] + s_col[3][tid];
            s_sigma[tid] = 1.0f / (256.0f * c);
        }
        __syncthreads();
        const float sg = s_sigma[jl];
        #pragma unroll
        for (int k = 0; k < 49; ++k)
            T[k] = s_delta[rq + 4*k] * E[k] * T[k] * sg;
    }

    const size_t base = (size_t)b * NM;
    if (ToutF){
        #pragma unroll
        for (int k = 0; k < 49; ++k)
            ToutF[base + (size_t)(rq + 4*k)*M_TOK + jg] = T[k];
    }
    if (Gh){
        #pragma unroll
        for (int k = 0; k < 49; ++k){
            __nv_bfloat16 h, l; split_bf16(T[k], h, l);
            const size_t o = base + (size_t)(rq + 4*k)*M_TOK + jg;
            Gh[o] = h; Gl[o] = l;
        }
    }

    if (dotOut){
        float dot = 0.f;
        #pragma unroll
        for (int k = 0; k < 49; ++k)
            dot += C[(rq + 4*k)*M_TOK + jg] * T[k];
        #pragma unroll
        for (int o = 16; o; o >>= 1) dot += __shfl_xor_sync(0xffffffffu, dot, o);
        if (lane == 0) s_dred[wid] = dot;
        __syncthreads();
        if (tid == 0){
            float t = 0.f;
            for (int w = 0; w < 8; ++w) t += s_dred[w];
            s_dotpart = t;
        }
        cluster.sync();
        if (rank == 0 && tid == 0){
            float t = 0.f;
            #pragma unroll
            for (int r = 0; r < 4; ++r)
                t += *cluster.map_shared_rank(&s_dotpart, r);
            dotOut[b] = t;
        }
    }
    cluster.sync();
}

__global__ void final_kernel(float* __restrict__ outp){
    int t = threadIdx.x;
    float wd = g_dotwd[t];
    float gw = g_dotgw[t];
    #pragma unroll
    for (int o = 16; o; o >>= 1){
        wd += __shfl_xor_sync(0xffffffffu, wd, o);
        gw += __shfl_xor_sync(0xffffffffu, gw, o);
    }
    if (t == 0)
        outp[0] = 0.1f*(gw * (1.0f/B_)) - 0.1f*(wd * (1.0f/B_));
}

// ---------------- host launcher ----------------
extern "C" void kernel_launch(void* const* d_in, const int* in_sizes, int n_in,
                              void* d_out, int out_size)
{
    const float* img     = (const float*)d_in[0];
    const float* tok     = (const float*)d_in[1];
    const float* tokmask = (const float*)d_in[2];
    const int*   tdm     = (const int*)d_in[3];
    const int*   irm     = (const int*)d_in[4];
    float* out = (float*)d_out;                    // [1 | T_wd | T_gwd]
    float* outTwd  = out + 1;
    float* outTgwd = out + 1 + (size_t)B_*NM;

    __nv_bfloat16 *xh, *xl, *yh, *yl, *csh, *csl, *cth, *ctl, *gh, *gl, *th, *tl;
    float *Cxy, *Cs, *Ct, *Cg, *crow, *ccol, *dwd, *dgw;
    cudaGetSymbolAddress((void**)&xh,  g_xh);
    cudaGetSymbolAddress((void**)&xl,  g_xl);
    cudaGetSymbolAddress((void**)&yh,  g_yh);
    cudaGetSymbolAddress((void**)&yl,  g_yl);
    cudaGetSymbolAddress((void**)&csh, g_Csh);
    cudaGetSymbolAddress((void**)&csl, g_Csl);
    cudaGetSymbolAddress((void**)&cth, g_Cth);
    cudaGetSymbolAddress((void**)&ctl, g_Ctl);
    cudaGetSymbolAddress((void**)&gh,  g_gamh);
    cudaGetSymbolAddress((void**)&gl,  g_gaml);
    cudaGetSymbolAddress((void**)&th,  g_tmph);
    cudaGetSymbolAddress((void**)&tl,  g_tmpl);
    cudaGetSymbolAddress((void**)&Cxy, g_Cxy);
    cudaGetSymbolAddress((void**)&Cs,  g_Cs);
    cudaGetSymbolAddress((void**)&Ct,  g_Ct);
    cudaGetSymbolAddress((void**)&Cg,  g_Cg);
    cudaGetSymbolAddress((void**)&crow, g_cstrow);
    cudaGetSymbolAddress((void**)&ccol, g_cstcol);
    cudaGetSymbolAddress((void**)&dwd, g_dotwd);
    cudaGetSymbolAddress((void**)&dgw, g_dotgw);

    cudaFuncSetAttribute(cosmma_kernel, cudaFuncAttributeMaxDynamicSharedMemorySize, COS_DSM);
    cudaFuncSetAttribute(gwmma1_kernel, cudaFuncAttributeMaxDynamicSharedMemorySize, GW1_DSM);
    cudaFuncSetAttribute(gwmma2_kernel, cudaFuncAttributeMaxDynamicSharedMemorySize, COS_DSM);

    init_kernel<<<1, 64>>>();
    normalize_kernel<<<B_*N_IMG, 256>>>(img, nullptr, xh, xl, N_IMG);
    normalize_kernel<<<B_*M_TOK, 256>>>(tok, tokmask, yh, yl, M_TOK);

    cosmma_kernel<<<dim3(2,4,B_), 256, COS_DSM>>>(xh, xl, yh, yl, Cxy, N_IMG, M_TOK, 0);
    cosmma_kernel<<<dim3(2,4,B_), 256, COS_DSM>>>(xh, xl, xh, xl, Cs,  N_IMG, N_IMG, 1);
    cosmma_kernel<<<dim3(2,4,B_), 256, COS_DSM>>>(yh, yl, yh, yl, Ct,  M_TOK, M_TOK, 2);

    thresh_kernel<<<1024, 256>>>(Cxy, B_*NM, 0);
    threshsplit_kernel<<<1024, 256>>>(Cs, irm, csh, csl, N_IMG, N_IMG, KPAD, 1);
    threshsplit_kernel<<<1024, 256>>>(Ct, tdm, cth, ctl, M_TOK, M_TOK, M_TOK, 2);

    ipot_kernel<<<dim3(4,B_), 256>>>(Cxy, outTwd, nullptr, nullptr, dwd);

    rowmeansq_kernel<<<B_*N_IMG, 256>>>(Cs, crow, N_IMG);
    rowmeansq_kernel<<<B_*M_TOK, 256>>>(Ct, ccol, M_TOK);
    fillsplit_kernel<<<512, 256>>>(gh, gl, 1.0f/(float)NM, B_*NM);

    for (int it = 0; it < 6; ++it){
        gwmma1_kernel<<<dim3(2,4,B_), 256, GW1_DSM>>>(csh, csl, gh, gl, th, tl);
        const bool last = (it == 5);
        gwmma2_kernel<<<dim3(2,4,B_), 256, COS_DSM>>>(th, tl, cth, ctl, Cg, crow, ccol,
                                                      last ? outTgwd : nullptr, dgw);
        if (it < 5)
            ipot_kernel<<<dim3(4,B_), 256>>>(Cg, (it == 4) ? outTgwd : nullptr, gh, gl, nullptr);
    }

    final_kernel<<<1, 32>>>(out);
}